// round 4
// baseline (speedup 1.0000x reference)
#include <cuda_runtime.h>
#include <math.h>

#define BTOT 4
#define CINV 128
#define HHV 64
#define WWV 64
#define PLV 256
#define ATTV 64
#define RRV 16
#define STEPSV 6
#define EPSV 1e-6f
#define MTOT (BTOT*HHV*WWV)   /* 16384 */
#define HWV (HHV*WWV)         /* 4096 */

// ---------------- scratch (device globals; no runtime allocation) ----------------
__device__ float g_y[MTOT*PLV];      // conv1 output, NHWC [pix][p]
__device__ float g_xm[MTOT*PLV];     // depthwise+bias output, NHWC
__device__ float g_xl[MTOT*PLV];     // relu(lower) output
__device__ float g_feat[MTOT*PLV];   // relu(xm+xr)
__device__ float g_w1t[CINV*PLV];    // conv1_w transposed [c][p]
__device__ float g_lwt[PLV*PLV];     // lower_w transposed [k][n]
__device__ float g_fwt[PLV*CINV];    // fc_w transposed [p][o]
__device__ float g_att[BTOT*PLV];
__device__ float g_pool_sum[BTOT*PLV];
__device__ int   g_pool_max[BTOT*PLV];

// ---------------- init: zero pools + transpose weights ----------------
__global__ void init_kernel(const float* __restrict__ w1,
                            const float* __restrict__ lw,
                            const float* __restrict__ fw)
{
    int i = blockIdx.x * 256 + threadIdx.x;     // grid 256 -> 65536 threads
    if (i < BTOT*PLV) { g_pool_sum[i] = 0.f; g_pool_max[i] = 0; }
    if (i < CINV*PLV) { int c = i / PLV, p = i % PLV; g_w1t[i] = w1[p*CINV + c]; }
    if (i < PLV*PLV)  { int k = i / PLV, n = i % PLV; g_lwt[i] = lw[n*PLV + k]; }
    if (i < PLV*CINV) { int p = i / CINV, o = i % CINV; g_fwt[i] = fw[o*PLV + p]; }
}

// ---------------- tiled SIMT GEMM (128x128 tile, 8x8 per thread, ktile 16) --------
// MODE 0: y = x @ w1t            (A = x, k-major layout; C = g_y)
// MODE 1: xl = relu(xm@lwt + b)  (A = g_xm row-major; C = g_xl)
// MODE 2: out = (feat*att)@fwt+b (A = g_feat row-major scaled by g_att; C = param, NCHW)
template<int KDIM, int MODE, int ALAYOUT>
__global__ __launch_bounds__(256, 2)
void gemm_kernel(const float* __restrict__ Aparam, const float* __restrict__ bias,
                 float* __restrict__ Cparam, int Ncols)
{
    const float* A  = (MODE==0) ? Aparam : (MODE==1) ? g_xm : g_feat;
    const float* Bt = (MODE==0) ? g_w1t  : (MODE==1) ? g_lwt : g_fwt;
    float*       C  = (MODE==0) ? g_y    : (MODE==1) ? g_xl  : Cparam;

    __shared__ float As[16][132];
    __shared__ float Bs[16][132];
    const int m0 = blockIdx.x * 128;
    const int n0 = blockIdx.y * 128;
    const int t  = threadIdx.x;
    const int tx = t & 15;
    const int ty = t >> 4;
    const int batch = m0 >> 12;

    float acc[8][8];
#pragma unroll
    for (int i = 0; i < 8; i++)
#pragma unroll
        for (int j = 0; j < 8; j++) acc[i][j] = 0.f;

    for (int k0 = 0; k0 < KDIM; k0 += 16) {
        if (ALAYOUT == 0) {
#pragma unroll
            for (int r = 0; r < 2; r++) {
                const int idx = t + 256*r;
                const int ka = idx >> 5, mv = (idx & 31) << 2;
                *(float4*)&As[ka][mv] =
                    *(const float4*)(A + (size_t)batch*KDIM*HWV
                                     + (size_t)(k0+ka)*HWV + (m0 & (HWV-1)) + mv);
            }
        } else {
#pragma unroll
            for (int r = 0; r < 2; r++) {
                const int idx = t + 256*r;
                const int ma = idx >> 2, kv = (idx & 3) << 2;
                float4 v = *(const float4*)(A + (size_t)(m0+ma)*KDIM + k0 + kv);
                if (MODE == 2) {
                    const float4 sc = *(const float4*)(g_att + batch*PLV + k0 + kv);
                    v.x *= sc.x; v.y *= sc.y; v.z *= sc.z; v.w *= sc.w;
                }
                As[kv+0][ma] = v.x; As[kv+1][ma] = v.y;
                As[kv+2][ma] = v.z; As[kv+3][ma] = v.w;
            }
        }
#pragma unroll
        for (int r = 0; r < 2; r++) {
            const int idx = t + 256*r;
            const int kb = idx >> 5, nv = (idx & 31) << 2;
            *(float4*)&Bs[kb][nv] = *(const float4*)(Bt + (size_t)(k0+kb)*Ncols + n0 + nv);
        }
        __syncthreads();
#pragma unroll
        for (int k = 0; k < 16; k++) {
            float4 a0 = *(float4*)&As[k][ty<<2];
            float4 a1 = *(float4*)&As[k][64 + (ty<<2)];
            float4 b0 = *(float4*)&Bs[k][tx<<2];
            float4 b1 = *(float4*)&Bs[k][64 + (tx<<2)];
            float am[8] = {a0.x,a0.y,a0.z,a0.w,a1.x,a1.y,a1.z,a1.w};
            float bn[8] = {b0.x,b0.y,b0.z,b0.w,b1.x,b1.y,b1.z,b1.w};
#pragma unroll
            for (int i = 0; i < 8; i++)
#pragma unroll
                for (int j = 0; j < 8; j++)
                    acc[i][j] = fmaf(am[i], bn[j], acc[i][j]);
        }
        __syncthreads();
    }

#pragma unroll
    for (int i = 0; i < 8; i++) {
        const int mr = (i < 4) ? ((ty<<2) + i) : (64 + (ty<<2) + i - 4);
        const int m  = m0 + mr;
#pragma unroll
        for (int jj = 0; jj < 2; jj++) {
            float4 v;
            v.x = acc[i][jj*4+0]; v.y = acc[i][jj*4+1];
            v.z = acc[i][jj*4+2]; v.w = acc[i][jj*4+3];
            const int n = n0 + (tx<<2) + jj*64;
            if (MODE == 0) {
                *(float4*)&C[(size_t)m*Ncols + n] = v;
            } else if (MODE == 1) {
                const float4 bb = *(const float4*)(bias + n);
                v.x = fmaxf(v.x + bb.x, 0.f);
                v.y = fmaxf(v.y + bb.y, 0.f);
                v.z = fmaxf(v.z + bb.z, 0.f);
                v.w = fmaxf(v.w + bb.w, 0.f);
                *(float4*)&C[(size_t)m*Ncols + n] = v;
            } else {
                const int pix = m & (HWV-1);
#pragma unroll
                for (int qq = 0; qq < 4; qq++) {
                    C[(size_t)(batch*CINV + n + qq)*HWV + pix] = acc[i][jj*4+qq] + bias[n+qq];
                }
            }
        }
    }
}

// ---------------- depthwise 3x3 + bias, NHWC ----------------
__global__ __launch_bounds__(256)
void dw_kernel(const float* __restrict__ w3, const float* __restrict__ b3)
{
    const int p = threadIdx.x;
    float wv[9];
#pragma unroll
    for (int j = 0; j < 9; j++) wv[j] = w3[p*9 + j];
    const float bb = b3[p];
    const int base = blockIdx.x * 4;
    for (int q = 0; q < 4; q++) {
        const int pix = base + q;
        const int b = pix >> 12, hw = pix & 4095, h = hw >> 6, w = hw & 63;
        float acc = bb;
#pragma unroll
        for (int ky = 0; ky < 3; ky++) {
            const int hh = h + ky - 1;
            if (hh < 0 || hh >= HHV) continue;
#pragma unroll
            for (int kx = 0; kx < 3; kx++) {
                const int ww = w + kx - 1;
                if (ww < 0 || ww >= WWV) continue;
                acc = fmaf(g_y[(size_t)((b<<12) + (hh<<6) + ww)*PLV + p], wv[ky*3+kx], acc);
            }
        }
        g_xm[(size_t)pix*PLV + p] = acc;
    }
}

// ---------------- FAST EM: scalar path for r-uniform bases (one warp / pixel) -----
// If all 16 initial b_r are bit-equal (true for uniform[0,1) init: v/max(v,1e-12)
// == 1.0 exactly), coef stays uniform across r by induction (all per-r arithmetic
// is identical; sums of 16 equal fp values are exact *16). The EM collapses to a
// scalar recurrence. Non-uniform warps are skipped here; em_general handles them.
__global__ __launch_bounds__(512)
void em_fast(const float* __restrict__ binit)
{
    __shared__ float bsum[PLV];
    __shared__ int   bmx[PLV];
    const int t = threadIdx.x;
    if (t < PLV) { bsum[t] = 0.f; bmx[t] = 0; }
    __syncthreads();

    const int w = t >> 5, lane = t & 31;
    const int m = blockIdx.x * 16 + w;

    float bv = 1.f;
    if (lane < RRV) {
        const float v = binit[m*RRV + lane];
        bv = v / fmaxf(fabsf(v), 1e-12f);
    }
    const float b0 = __shfl_sync(0xffffffffu, bv, 0);
    const bool uni = __all_sync(0xffffffffu, (lane >= RRV) || (bv == b0));

    if (uni) {
        float b = b0;
        float x[8], cf[8];
        {
            const float4 v0 = *(const float4*)(g_xl + (size_t)m*PLV + lane*8);
            const float4 v1 = *(const float4*)(g_xl + (size_t)m*PLV + lane*8 + 4);
            x[0]=v0.x; x[1]=v0.y; x[2]=v0.z; x[3]=v0.w;
            x[4]=v1.x; x[5]=v1.y; x[6]=v1.z; x[7]=v1.w;
        }
#pragma unroll
        for (int j = 0; j < 8; j++) cf[j] = 0.0625f;   // softmax of equal logits

#pragma unroll
        for (int step = 0; step < STEPSV; step++) {
            // coef update: den = 16*cf*b*b + eps ; cf *= (x*b)/den
            float ps = 0.f, qs = 0.f;
#pragma unroll
            for (int j = 0; j < 8; j++) {
                const float tb  = cf[j] * b;
                const float den = fmaf(16.f*tb, b, EPSV);
                const float num = x[j] * b;
                cf[j] = cf[j] * num * __fdividef(1.f, den);
                ps = fmaf(x[j],  cf[j], ps);     // p = sum x*cf
                qs = fmaf(cf[j], cf[j], qs);     // q' = sum cf^2  (q = 16*b*q')
            }
#pragma unroll
            for (int off = 16; off > 0; off >>= 1) {
                ps += __shfl_xor_sync(0xffffffffu, ps, off);
                qs += __shfl_xor_sync(0xffffffffu, qs, off);
            }
            const float den = fmaf(16.f*b, qs, EPSV);
            b = b * ps * __fdividef(1.f, den);
        }
        // final coef update
#pragma unroll
        for (int j = 0; j < 8; j++) {
            const float tb  = cf[j] * b;
            const float den = fmaf(16.f*tb, b, EPSV);
            const float num = x[j] * b;
            cf[j] = cf[j] * num * __fdividef(1.f, den);
        }
        // xr = 16*b*cf ; feat = relu(xm + xr) ; pooling
        const float4 m0v = *(const float4*)(g_xm + (size_t)m*PLV + lane*8);
        const float4 m1v = *(const float4*)(g_xm + (size_t)m*PLV + lane*8 + 4);
        const float xm8[8] = {m0v.x,m0v.y,m0v.z,m0v.w,m1v.x,m1v.y,m1v.z,m1v.w};
        float f[8];
#pragma unroll
        for (int j = 0; j < 8; j++) {
            f[j] = fmaxf(fmaf(16.f*b, cf[j], xm8[j]), 0.f);
            const int n = lane*8 + j;
            atomicAdd(&bsum[n], f[j]);
            atomicMax(&bmx[n], __float_as_int(f[j]));
        }
        float4 o0 = make_float4(f[0],f[1],f[2],f[3]);
        float4 o1 = make_float4(f[4],f[5],f[6],f[7]);
        *(float4*)(g_feat + (size_t)m*PLV + lane*8)     = o0;
        *(float4*)(g_feat + (size_t)m*PLV + lane*8 + 4) = o1;
    }
    __syncthreads();
    if (t < PLV) {
        const int bb = (blockIdx.x * 16) >> 12;
        atomicAdd(&g_pool_sum[bb*PLV + t], bsum[t]);
        atomicMax(&g_pool_max[bb*PLV + t], bmx[t]);
    }
}

// ---------------- GENERAL EM (fallback for non-uniform warps) ----------------
__global__ __launch_bounds__(256, 1)
void em_general(const float* __restrict__ binit)
{
    __shared__ float bsum[PLV];
    __shared__ int   bmx[PLV];
    const int t = threadIdx.x;
    bsum[t] = 0.f; bmx[t] = 0;
    __syncthreads();

    const int w = t >> 5, lane = t & 31;
    const int m = blockIdx.x * 8 + w;

    float b[RRV];
#pragma unroll
    for (int r = 0; r < RRV; r++) {
        const float v = binit[m*RRV + r];
        b[r] = v / fmaxf(fabsf(v), 1e-12f);
    }
    bool uni = true;
#pragma unroll
    for (int r = 1; r < RRV; r++) uni &= (b[r] == b[0]);

    bool did = false;
    if (!uni) {
        did = true;
        float x[8];
#pragma unroll
        for (int j = 0; j < 8; j++) x[j] = g_xl[(size_t)m*PLV + lane + 32*j];

        float cf[8][RRV];
#pragma unroll
        for (int j = 0; j < 8; j++) {
            const float xn = x[j];
            float tv[RRV]; float mx = -3.4e38f;
#pragma unroll
            for (int r = 0; r < RRV; r++) { tv[r] = xn * b[r]; mx = fmaxf(mx, tv[r]); }
            float s = 0.f;
#pragma unroll
            for (int r = 0; r < RRV; r++) { const float e = __expf(tv[r]-mx); cf[j][r]=e; s+=e; }
            const float inv = __fdividef(1.f, s);
#pragma unroll
            for (int r = 0; r < RRV; r++) cf[j][r] *= inv;
        }
        for (int step = 0; step < STEPSV; step++) {
#pragma unroll
            for (int j = 0; j < 8; j++) {
                float s = 0.f;
#pragma unroll
                for (int r = 0; r < RRV; r++) s = fmaf(cf[j][r], b[r], s);
                const float xn = x[j];
#pragma unroll
                for (int r = 0; r < RRV; r++) {
                    const float num = xn * b[r];
                    const float den = fmaf(s, b[r], EPSV);
                    cf[j][r] = cf[j][r] * num * __fdividef(1.f, den);
                }
            }
            float p[RRV], q[RRV];
#pragma unroll
            for (int r = 0; r < RRV; r++) { p[r]=0.f; q[r]=0.f; }
#pragma unroll
            for (int j = 0; j < 8; j++) {
                float sp = 0.f;
#pragma unroll
                for (int r = 0; r < RRV; r++) sp = fmaf(cf[j][r], b[r], sp);
                const float xn = x[j];
#pragma unroll
                for (int r = 0; r < RRV; r++) {
                    p[r] = fmaf(xn, cf[j][r], p[r]);
                    q[r] = fmaf(sp, cf[j][r], q[r]);
                }
            }
#pragma unroll
            for (int off = 16; off > 0; off >>= 1) {
#pragma unroll
                for (int r = 0; r < RRV; r++) {
                    p[r] += __shfl_xor_sync(0xffffffffu, p[r], off);
                    q[r] += __shfl_xor_sync(0xffffffffu, q[r], off);
                }
            }
#pragma unroll
            for (int r = 0; r < RRV; r++)
                b[r] = b[r] * p[r] * __fdividef(1.f, q[r] + EPSV);
        }
#pragma unroll
        for (int j = 0; j < 8; j++) {
            float s = 0.f;
#pragma unroll
            for (int r = 0; r < RRV; r++) s = fmaf(cf[j][r], b[r], s);
            const float xn = x[j];
#pragma unroll
            for (int r = 0; r < RRV; r++) {
                const float num = xn * b[r];
                const float den = fmaf(s, b[r], EPSV);
                cf[j][r] = cf[j][r] * num * __fdividef(1.f, den);
            }
        }
#pragma unroll
        for (int j = 0; j < 8; j++) {
            float xr = 0.f;
#pragma unroll
            for (int r = 0; r < RRV; r++) xr = fmaf(b[r], cf[j][r], xr);
            const int n = lane + 32*j;
            const float f = fmaxf(g_xm[(size_t)m*PLV + n] + xr, 0.f);
            g_feat[(size_t)m*PLV + n] = f;
            atomicAdd(&bsum[n], f);
            atomicMax(&bmx[n], __float_as_int(f));
        }
    }
    __syncthreads();
    if (__syncthreads_or(did)) {
        const int bb = (blockIdx.x * 8) >> 12;
        atomicAdd(&g_pool_sum[bb*PLV + t], bsum[t]);
        atomicMax(&g_pool_max[bb*PLV + t], bmx[t]);
    }
}

// ---------------- channel attention ----------------
__global__ __launch_bounds__(256)
void ca_kernel(const float* __restrict__ ca1, const float* __restrict__ ca2,
               float* __restrict__ out)
{
    const int b = blockIdx.x;
    const int t = threadIdx.x;
    __shared__ float sAvg[PLV], sMx[PLV], h1[ATTV];
    sAvg[t] = g_pool_sum[b*PLV + t] * (1.0f/(float)HWV);
    sMx[t]  = __int_as_float(g_pool_max[b*PLV + t]);
    __syncthreads();
    if (t < ATTV) {
        float a1 = 0.f, a2 = 0.f;
        for (int p = 0; p < PLV; p++) {
            const float wv = ca1[t*PLV + p];
            a1 = fmaf(wv, sAvg[p], a1);
            a2 = fmaf(wv, sMx[p],  a2);
        }
        h1[t] = fmaxf(a1, 0.f) + fmaxf(a2, 0.f);   // second layer is linear -> sum first
    }
    __syncthreads();
    float v = 0.f;
    for (int a = 0; a < ATTV; a++) v = fmaf(h1[a], ca2[t*ATTV + a], v);
    const float att = __fdividef(1.f, 1.f + __expf(-v));
    g_att[b*PLV + t] = att;
    out[(size_t)BTOT*CINV*HWV + b*PLV + t] = att;   // att output after `out` block
}

// ---------------- launch ----------------
extern "C" void kernel_launch(void* const* d_in, const int* in_sizes, int n_in,
                              void* d_out, int out_size)
{
    const float* x       = (const float*)d_in[0];
    const float* conv1_w = (const float*)d_in[1];
    const float* conv3_w = (const float*)d_in[2];
    const float* conv3_b = (const float*)d_in[3];
    const float* lower_w = (const float*)d_in[4];
    const float* lower_b = (const float*)d_in[5];
    const float* ca1_w   = (const float*)d_in[6];
    const float* ca2_w   = (const float*)d_in[7];
    const float* fc_w    = (const float*)d_in[8];
    const float* fc_b    = (const float*)d_in[9];
    const float* bases   = (const float*)d_in[10];
    float* out = (float*)d_out;

    init_kernel<<<256, 256>>>(conv1_w, lower_w, fc_w);
    gemm_kernel<CINV, 0, 0><<<dim3(MTOT/128, PLV/128), 256>>>(x, nullptr, nullptr, PLV);
    dw_kernel<<<MTOT/4, 256>>>(conv3_w, conv3_b);
    gemm_kernel<PLV, 1, 1><<<dim3(MTOT/128, PLV/128), 256>>>(nullptr, lower_b, nullptr, PLV);
    em_fast<<<MTOT/16, 512>>>(bases);
    em_general<<<MTOT/8, 256>>>(bases);
    ca_kernel<<<BTOT, 256>>>(ca1_w, ca2_w, out);
    gemm_kernel<PLV, 2, 1><<<dim3(MTOT/128, 1), 256>>>(nullptr, fc_b, out, CINV);
}

// round 5
// speedup vs baseline: 1.0983x; 1.0983x over previous
#include <cuda_runtime.h>
#include <math.h>

#define BTOT 4
#define CINV 128
#define HHV 64
#define WWV 64
#define PLV 256
#define ATTV 64
#define RRV 16
#define STEPSV 6
#define EPSV 1e-6f
#define MTOT (BTOT*HHV*WWV)   /* 16384 */
#define HWV (HHV*WWV)         /* 4096 */

// ---------------- scratch (device globals; no runtime allocation) ----------------
__device__ float g_y[MTOT*PLV];      // conv1 output, NHWC [pix][p]
__device__ float g_xm[MTOT*PLV];     // depthwise+bias output, NHWC
__device__ float g_xl[MTOT*PLV];     // relu(lower) output
__device__ float g_feat[MTOT*PLV];   // relu(xm+xr)
__device__ float g_w1t[CINV*PLV];    // conv1_w transposed [c][p]
__device__ float g_lwt[PLV*PLV];     // lower_w transposed [k][n]
__device__ float g_fwt[PLV*CINV];    // fc_w transposed [p][o]
__device__ float g_att[BTOT*PLV];
__device__ float g_pool_sum[BTOT*PLV];
__device__ int   g_pool_max[BTOT*PLV];

// ---------------- init: zero pools + transpose weights ----------------
__global__ void init_kernel(const float* __restrict__ w1,
                            const float* __restrict__ lw,
                            const float* __restrict__ fw)
{
    int i = blockIdx.x * 256 + threadIdx.x;     // grid 256 -> 65536 threads
    if (i < BTOT*PLV) { g_pool_sum[i] = 0.f; g_pool_max[i] = 0; }
    if (i < CINV*PLV) { int c = i / PLV, p = i % PLV; g_w1t[i] = w1[p*CINV + c]; }
    if (i < PLV*PLV)  { int k = i / PLV, n = i % PLV; g_lwt[i] = lw[n*PLV + k]; }
    if (i < PLV*CINV) { int p = i / CINV, o = i % CINV; g_fwt[i] = fw[o*PLV + p]; }
}

// ------------- double-buffered tiled SIMT GEMM (128x128 tile, 8x8/thread) --------
// MODE 0: y = x @ w1t            (A = x, k-major layout; C = g_y, NHWC)
// MODE 1: xl = relu(xm@lwt + b)  (A = g_xm row-major; C = g_xl, NHWC)
// MODE 2: out = (feat*att)@fwt+b (A = g_feat row-major scaled by g_att; C NCHW)
template<int KDIM, int MODE, int ALAYOUT>
__global__ __launch_bounds__(256, 2)
void gemm_kernel(const float* __restrict__ Aparam, const float* __restrict__ bias,
                 float* __restrict__ Cparam, int Ncols)
{
    const float* A  = (MODE==0) ? Aparam : (MODE==1) ? g_xm : g_feat;
    const float* Bt = (MODE==0) ? g_w1t  : (MODE==1) ? g_lwt : g_fwt;
    float*       C  = (MODE==0) ? g_y    : (MODE==1) ? g_xl  : Cparam;

    __shared__ float As[2][16][132];
    __shared__ float Bs[2][16][132];

    const int m0 = blockIdx.x * 128;
    const int n0 = blockIdx.y * 128;
    const int t  = threadIdx.x;
    const int tx = t & 15;
    const int ty = t >> 4;
    const int batch = m0 >> 12;

    float4 pa[2], pb[2];

    // ---- prefetch helpers (inlined twice below) ----
#define LOAD_TILE(K0)                                                            \
    do {                                                                         \
        if (ALAYOUT == 0) {                                                      \
            _Pragma("unroll")                                                    \
            for (int r = 0; r < 2; r++) {                                        \
                const int idx = t + 256*r;                                       \
                const int ka = idx >> 5, mv = (idx & 31) << 2;                   \
                pa[r] = *(const float4*)(A + (size_t)batch*KDIM*HWV              \
                         + (size_t)((K0)+ka)*HWV + (m0 & (HWV-1)) + mv);         \
            }                                                                    \
        } else {                                                                 \
            _Pragma("unroll")                                                    \
            for (int r = 0; r < 2; r++) {                                        \
                const int idx = t + 256*r;                                       \
                const int ma = idx >> 2, kv = (idx & 3) << 2;                    \
                float4 v = *(const float4*)(A + (size_t)(m0+ma)*KDIM + (K0)+kv); \
                if (MODE == 2) {                                                 \
                    const float4 sc = *(const float4*)(g_att + batch*PLV + (K0)+kv); \
                    v.x *= sc.x; v.y *= sc.y; v.z *= sc.z; v.w *= sc.w;          \
                }                                                                \
                pa[r] = v;                                                       \
            }                                                                    \
        }                                                                        \
        _Pragma("unroll")                                                        \
        for (int r = 0; r < 2; r++) {                                            \
            const int idx = t + 256*r;                                           \
            const int kb = idx >> 5, nv = (idx & 31) << 2;                       \
            pb[r] = *(const float4*)(Bt + (size_t)((K0)+kb)*Ncols + n0 + nv);    \
        }                                                                        \
    } while (0)

#define STORE_TILE(BUF)                                                          \
    do {                                                                         \
        if (ALAYOUT == 0) {                                                      \
            _Pragma("unroll")                                                    \
            for (int r = 0; r < 2; r++) {                                        \
                const int idx = t + 256*r;                                       \
                const int ka = idx >> 5, mv = (idx & 31) << 2;                   \
                *(float4*)&As[BUF][ka][mv] = pa[r];                              \
            }                                                                    \
        } else {                                                                 \
            _Pragma("unroll")                                                    \
            for (int r = 0; r < 2; r++) {                                        \
                const int idx = t + 256*r;                                       \
                const int ma = idx >> 2, kv = (idx & 3) << 2;                    \
                As[BUF][kv+0][ma] = pa[r].x; As[BUF][kv+1][ma] = pa[r].y;        \
                As[BUF][kv+2][ma] = pa[r].z; As[BUF][kv+3][ma] = pa[r].w;        \
            }                                                                    \
        }                                                                        \
        _Pragma("unroll")                                                        \
        for (int r = 0; r < 2; r++) {                                            \
            const int idx = t + 256*r;                                           \
            const int kb = idx >> 5, nv = (idx & 31) << 2;                       \
            *(float4*)&Bs[BUF][kb][nv] = pb[r];                                  \
        }                                                                        \
    } while (0)

    float acc[8][8];
#pragma unroll
    for (int i = 0; i < 8; i++)
#pragma unroll
        for (int j = 0; j < 8; j++) acc[i][j] = 0.f;

    LOAD_TILE(0);
    STORE_TILE(0);
    __syncthreads();

    const int NK = KDIM / 16;
    int buf = 0;
#pragma unroll 1
    for (int it = 0; it < NK; it++) {
        if (it + 1 < NK) LOAD_TILE((it + 1) * 16);
#pragma unroll
        for (int k = 0; k < 16; k++) {
            float4 a0 = *(float4*)&As[buf][k][ty<<2];
            float4 a1 = *(float4*)&As[buf][k][64 + (ty<<2)];
            float4 b0 = *(float4*)&Bs[buf][k][tx<<2];
            float4 b1 = *(float4*)&Bs[buf][k][64 + (tx<<2)];
            float am[8] = {a0.x,a0.y,a0.z,a0.w,a1.x,a1.y,a1.z,a1.w};
            float bn[8] = {b0.x,b0.y,b0.z,b0.w,b1.x,b1.y,b1.z,b1.w};
#pragma unroll
            for (int i = 0; i < 8; i++)
#pragma unroll
                for (int j = 0; j < 8; j++)
                    acc[i][j] = fmaf(am[i], bn[j], acc[i][j]);
        }
        if (it + 1 < NK) {
            STORE_TILE(buf ^ 1);
            __syncthreads();
        }
        buf ^= 1;
    }
#undef LOAD_TILE
#undef STORE_TILE

    if (MODE != 2) {
#pragma unroll
        for (int i = 0; i < 8; i++) {
            const int mr = (i < 4) ? ((ty<<2) + i) : (64 + (ty<<2) + i - 4);
            const int m  = m0 + mr;
#pragma unroll
            for (int jj = 0; jj < 2; jj++) {
                float4 v;
                v.x = acc[i][jj*4+0]; v.y = acc[i][jj*4+1];
                v.z = acc[i][jj*4+2]; v.w = acc[i][jj*4+3];
                const int n = n0 + (tx<<2) + jj*64;
                if (MODE == 1) {
                    const float4 bb = *(const float4*)(bias + n);
                    v.x = fmaxf(v.x + bb.x, 0.f);
                    v.y = fmaxf(v.y + bb.y, 0.f);
                    v.z = fmaxf(v.z + bb.z, 0.f);
                    v.w = fmaxf(v.w + bb.w, 0.f);
                }
                *(float4*)&C[(size_t)m*Ncols + n] = v;
            }
        }
    } else {
        // stage per jj-half through smem so NCHW stores are coalesced
        float* st = &As[0][0][0];           // 128 x 65 staging (8320 floats <= 8448)
        const int pixbase = m0 & (HWV - 1);
        const int lane = t & 31, chb = t >> 5;
#pragma unroll
        for (int jj = 0; jj < 2; jj++) {
            __syncthreads();
#pragma unroll
            for (int i = 0; i < 8; i++) {
                const int mr = (i < 4) ? ((ty<<2) + i) : (64 + (ty<<2) + i - 4);
#pragma unroll
                for (int q = 0; q < 4; q++) {
                    const int n = (tx<<2) + q + jj*64;     // global channel 0..127
                    st[mr*65 + (tx<<2) + q] = acc[i][jj*4+q] + bias[n];
                }
            }
            __syncthreads();
#pragma unroll
            for (int cp = 0; cp < 8; cp++) {
                const int ch = chb + 8*cp;                 // 0..63 within half
#pragma unroll
                for (int pbk = 0; pbk < 4; pbk++) {
                    const int pix = pbk*32 + lane;
                    C[(size_t)(batch*CINV + jj*64 + ch)*HWV + pixbase + pix]
                        = st[pix*65 + ch];
                }
            }
        }
    }
}

// ------------- depthwise 3x3 + bias, NHWC, rolling 3-column window ---------------
// block = 256 threads (one channel each) x one 16-pixel row segment
__global__ __launch_bounds__(256)
void dw_kernel(const float* __restrict__ w3, const float* __restrict__ b3)
{
    const int p = threadIdx.x;
    float wv[9];
#pragma unroll
    for (int j = 0; j < 9; j++) wv[j] = w3[p*9 + j];
    const float bb = b3[p];

    const int pix0 = blockIdx.x * 16;
    const int b = pix0 >> 12, hw = pix0 & 4095, h = hw >> 6, w0 = hw & 63;
    const size_t rowm = (h > 0)      ? ((size_t)((b<<12) + ((h-1)<<6)) * PLV + p) : 0;
    const size_t rowc = (size_t)((b<<12) + (h<<6)) * PLV + p;
    const size_t rowp = (h < HHV-1)  ? ((size_t)((b<<12) + ((h+1)<<6)) * PLV + p) : 0;
    const bool hm = (h > 0), hp = (h < HHV-1);

    float a0,a1,a2, c0,c1,c2;
    // column w0-1
    if (w0 > 0) {
        a0 = hm ? g_y[rowm + (size_t)(w0-1)*PLV] : 0.f;
        a1 =      g_y[rowc + (size_t)(w0-1)*PLV];
        a2 = hp ? g_y[rowp + (size_t)(w0-1)*PLV] : 0.f;
    } else { a0 = a1 = a2 = 0.f; }
    // column w0
    c0 = hm ? g_y[rowm + (size_t)w0*PLV] : 0.f;
    c1 =      g_y[rowc + (size_t)w0*PLV];
    c2 = hp ? g_y[rowp + (size_t)w0*PLV] : 0.f;

#pragma unroll
    for (int k = 0; k < 16; k++) {
        const int ww = w0 + k + 1;
        float n0v, n1v, n2v;
        if (ww < WWV) {
            n0v = hm ? g_y[rowm + (size_t)ww*PLV] : 0.f;
            n1v =      g_y[rowc + (size_t)ww*PLV];
            n2v = hp ? g_y[rowp + (size_t)ww*PLV] : 0.f;
        } else { n0v = n1v = n2v = 0.f; }

        float acc = bb;
        acc = fmaf(a0, wv[0], acc); acc = fmaf(c0, wv[1], acc); acc = fmaf(n0v, wv[2], acc);
        acc = fmaf(a1, wv[3], acc); acc = fmaf(c1, wv[4], acc); acc = fmaf(n1v, wv[5], acc);
        acc = fmaf(a2, wv[6], acc); acc = fmaf(c2, wv[7], acc); acc = fmaf(n2v, wv[8], acc);
        g_xm[(size_t)(pix0 + k)*PLV + p] = acc;

        a0 = c0; a1 = c1; a2 = c2;
        c0 = n0v; c1 = n1v; c2 = n2v;
    }
}

// ---------------- FAST EM: scalar path for r-uniform bases (one warp / pixel) -----
__global__ __launch_bounds__(512)
void em_fast(const float* __restrict__ binit)
{
    __shared__ float bsum[PLV];
    __shared__ int   bmx[PLV];
    const int t = threadIdx.x;
    if (t < PLV) { bsum[t] = 0.f; bmx[t] = 0; }
    __syncthreads();

    const int w = t >> 5, lane = t & 31;
    const int m = blockIdx.x * 16 + w;

    float bv = 1.f;
    if (lane < RRV) {
        const float v = binit[m*RRV + lane];
        bv = v / fmaxf(fabsf(v), 1e-12f);
    }
    const float b0 = __shfl_sync(0xffffffffu, bv, 0);
    const bool uni = __all_sync(0xffffffffu, (lane >= RRV) || (bv == b0));

    if (uni) {
        float b = b0;
        float x[8], cf[8];
        {
            const float4 v0 = *(const float4*)(g_xl + (size_t)m*PLV + lane*8);
            const float4 v1 = *(const float4*)(g_xl + (size_t)m*PLV + lane*8 + 4);
            x[0]=v0.x; x[1]=v0.y; x[2]=v0.z; x[3]=v0.w;
            x[4]=v1.x; x[5]=v1.y; x[6]=v1.z; x[7]=v1.w;
        }
#pragma unroll
        for (int j = 0; j < 8; j++) cf[j] = 0.0625f;   // softmax of equal logits

#pragma unroll
        for (int step = 0; step < STEPSV; step++) {
            float ps = 0.f, qs = 0.f;
#pragma unroll
            for (int j = 0; j < 8; j++) {
                const float tb  = cf[j] * b;
                const float den = fmaf(16.f*tb, b, EPSV);
                const float num = x[j] * b;
                cf[j] = cf[j] * num * __fdividef(1.f, den);
                ps = fmaf(x[j],  cf[j], ps);
                qs = fmaf(cf[j], cf[j], qs);
            }
#pragma unroll
            for (int off = 16; off > 0; off >>= 1) {
                ps += __shfl_xor_sync(0xffffffffu, ps, off);
                qs += __shfl_xor_sync(0xffffffffu, qs, off);
            }
            const float den = fmaf(16.f*b, qs, EPSV);
            b = b * ps * __fdividef(1.f, den);
        }
#pragma unroll
        for (int j = 0; j < 8; j++) {
            const float tb  = cf[j] * b;
            const float den = fmaf(16.f*tb, b, EPSV);
            const float num = x[j] * b;
            cf[j] = cf[j] * num * __fdividef(1.f, den);
        }
        const float4 m0v = *(const float4*)(g_xm + (size_t)m*PLV + lane*8);
        const float4 m1v = *(const float4*)(g_xm + (size_t)m*PLV + lane*8 + 4);
        const float xm8[8] = {m0v.x,m0v.y,m0v.z,m0v.w,m1v.x,m1v.y,m1v.z,m1v.w};
        float f[8];
#pragma unroll
        for (int j = 0; j < 8; j++) {
            f[j] = fmaxf(fmaf(16.f*b, cf[j], xm8[j]), 0.f);
            const int n = lane*8 + j;
            atomicAdd(&bsum[n], f[j]);
            atomicMax(&bmx[n], __float_as_int(f[j]));
        }
        float4 o0 = make_float4(f[0],f[1],f[2],f[3]);
        float4 o1 = make_float4(f[4],f[5],f[6],f[7]);
        *(float4*)(g_feat + (size_t)m*PLV + lane*8)     = o0;
        *(float4*)(g_feat + (size_t)m*PLV + lane*8 + 4) = o1;
    }
    __syncthreads();
    if (t < PLV) {
        const int bb = (blockIdx.x * 16) >> 12;
        atomicAdd(&g_pool_sum[bb*PLV + t], bsum[t]);
        atomicMax(&g_pool_max[bb*PLV + t], bmx[t]);
    }
}

// ---------------- GENERAL EM (fallback for non-uniform warps) ----------------
__global__ __launch_bounds__(256, 1)
void em_general(const float* __restrict__ binit)
{
    __shared__ float bsum[PLV];
    __shared__ int   bmx[PLV];
    const int t = threadIdx.x;
    bsum[t] = 0.f; bmx[t] = 0;
    __syncthreads();

    const int w = t >> 5, lane = t & 31;
    const int m = blockIdx.x * 8 + w;

    float b[RRV];
#pragma unroll
    for (int r = 0; r < RRV; r++) {
        const float v = binit[m*RRV + r];
        b[r] = v / fmaxf(fabsf(v), 1e-12f);
    }
    bool uni = true;
#pragma unroll
    for (int r = 1; r < RRV; r++) uni &= (b[r] == b[0]);

    bool did = false;
    if (!uni) {
        did = true;
        float x[8];
#pragma unroll
        for (int j = 0; j < 8; j++) x[j] = g_xl[(size_t)m*PLV + lane + 32*j];

        float cf[8][RRV];
#pragma unroll
        for (int j = 0; j < 8; j++) {
            const float xn = x[j];
            float tv[RRV]; float mx = -3.4e38f;
#pragma unroll
            for (int r = 0; r < RRV; r++) { tv[r] = xn * b[r]; mx = fmaxf(mx, tv[r]); }
            float s = 0.f;
#pragma unroll
            for (int r = 0; r < RRV; r++) { const float e = __expf(tv[r]-mx); cf[j][r]=e; s+=e; }
            const float inv = __fdividef(1.f, s);
#pragma unroll
            for (int r = 0; r < RRV; r++) cf[j][r] *= inv;
        }
        for (int step = 0; step < STEPSV; step++) {
#pragma unroll
            for (int j = 0; j < 8; j++) {
                float s = 0.f;
#pragma unroll
                for (int r = 0; r < RRV; r++) s = fmaf(cf[j][r], b[r], s);
                const float xn = x[j];
#pragma unroll
                for (int r = 0; r < RRV; r++) {
                    const float num = xn * b[r];
                    const float den = fmaf(s, b[r], EPSV);
                    cf[j][r] = cf[j][r] * num * __fdividef(1.f, den);
                }
            }
            float p[RRV], q[RRV];
#pragma unroll
            for (int r = 0; r < RRV; r++) { p[r]=0.f; q[r]=0.f; }
#pragma unroll
            for (int j = 0; j < 8; j++) {
                float sp = 0.f;
#pragma unroll
                for (int r = 0; r < RRV; r++) sp = fmaf(cf[j][r], b[r], sp);
                const float xn = x[j];
#pragma unroll
                for (int r = 0; r < RRV; r++) {
                    p[r] = fmaf(xn, cf[j][r], p[r]);
                    q[r] = fmaf(sp, cf[j][r], q[r]);
                }
            }
#pragma unroll
            for (int off = 16; off > 0; off >>= 1) {
#pragma unroll
                for (int r = 0; r < RRV; r++) {
                    p[r] += __shfl_xor_sync(0xffffffffu, p[r], off);
                    q[r] += __shfl_xor_sync(0xffffffffu, q[r], off);
                }
            }
#pragma unroll
            for (int r = 0; r < RRV; r++)
                b[r] = b[r] * p[r] * __fdividef(1.f, q[r] + EPSV);
        }
#pragma unroll
        for (int j = 0; j < 8; j++) {
            float s = 0.f;
#pragma unroll
            for (int r = 0; r < RRV; r++) s = fmaf(cf[j][r], b[r], s);
            const float xn = x[j];
#pragma unroll
            for (int r = 0; r < RRV; r++) {
                const float num = xn * b[r];
                const float den = fmaf(s, b[r], EPSV);
                cf[j][r] = cf[j][r] * num * __fdividef(1.f, den);
            }
        }
#pragma unroll
        for (int j = 0; j < 8; j++) {
            float xr = 0.f;
#pragma unroll
            for (int r = 0; r < RRV; r++) xr = fmaf(b[r], cf[j][r], xr);
            const int n = lane + 32*j;
            const float f = fmaxf(g_xm[(size_t)m*PLV + n] + xr, 0.f);
            g_feat[(size_t)m*PLV + n] = f;
            atomicAdd(&bsum[n], f);
            atomicMax(&bmx[n], __float_as_int(f));
        }
    }
    __syncthreads();
    if (__syncthreads_or(did)) {
        const int bb = (blockIdx.x * 8) >> 12;
        atomicAdd(&g_pool_sum[bb*PLV + t], bsum[t]);
        atomicMax(&g_pool_max[bb*PLV + t], bmx[t]);
    }
}

// ---------------- channel attention ----------------
__global__ __launch_bounds__(256)
void ca_kernel(const float* __restrict__ ca1, const float* __restrict__ ca2,
               float* __restrict__ out)
{
    const int b = blockIdx.x;
    const int t = threadIdx.x;
    __shared__ float sAvg[PLV], sMx[PLV], h1[ATTV];
    sAvg[t] = g_pool_sum[b*PLV + t] * (1.0f/(float)HWV);
    sMx[t]  = __int_as_float(g_pool_max[b*PLV + t]);
    __syncthreads();
    if (t < ATTV) {
        float a1 = 0.f, a2 = 0.f;
        for (int p = 0; p < PLV; p++) {
            const float wv = ca1[t*PLV + p];
            a1 = fmaf(wv, sAvg[p], a1);
            a2 = fmaf(wv, sMx[p],  a2);
        }
        h1[t] = fmaxf(a1, 0.f) + fmaxf(a2, 0.f);   // second layer is linear -> sum first
    }
    __syncthreads();
    float v = 0.f;
    for (int a = 0; a < ATTV; a++) v = fmaf(h1[a], ca2[t*ATTV + a], v);
    const float att = __fdividef(1.f, 1.f + __expf(-v));
    g_att[b*PLV + t] = att;
    out[(size_t)BTOT*CINV*HWV + b*PLV + t] = att;   // att output after `out` block
}

// ---------------- launch ----------------
extern "C" void kernel_launch(void* const* d_in, const int* in_sizes, int n_in,
                              void* d_out, int out_size)
{
    const float* x       = (const float*)d_in[0];
    const float* conv1_w = (const float*)d_in[1];
    const float* conv3_w = (const float*)d_in[2];
    const float* conv3_b = (const float*)d_in[3];
    const float* lower_w = (const float*)d_in[4];
    const float* lower_b = (const float*)d_in[5];
    const float* ca1_w   = (const float*)d_in[6];
    const float* ca2_w   = (const float*)d_in[7];
    const float* fc_w    = (const float*)d_in[8];
    const float* fc_b    = (const float*)d_in[9];
    const float* bases   = (const float*)d_in[10];
    float* out = (float*)d_out;

    init_kernel<<<256, 256>>>(conv1_w, lower_w, fc_w);
    gemm_kernel<CINV, 0, 0><<<dim3(MTOT/128, PLV/128), 256>>>(x, nullptr, nullptr, PLV);
    dw_kernel<<<MTOT/16, 256>>>(conv3_w, conv3_b);
    gemm_kernel<PLV, 1, 1><<<dim3(MTOT/128, PLV/128), 256>>>(nullptr, lower_b, nullptr, PLV);
    em_fast<<<MTOT/16, 512>>>(bases);
    em_general<<<MTOT/8, 256>>>(bases);
    ca_kernel<<<BTOT, 256>>>(ca1_w, ca2_w, out);
    gemm_kernel<PLV, 2, 1><<<dim3(MTOT/128, 1), 256>>>(nullptr, fc_b, out, CINV);
}

// round 7
// speedup vs baseline: 1.2107x; 1.1023x over previous
#include <cuda_runtime.h>
#include <cuda_bf16.h>
#include <math.h>
#include <stdint.h>

#define BTOT 4
#define CINV 128
#define HHV 64
#define WWV 64
#define PLV 256
#define ATTV 64
#define RRV 16
#define STEPSV 6
#define EPSV 1e-6f
#define MTOT (BTOT*HHV*WWV)   /* 16384 */
#define HWV (HHV*WWV)         /* 4096 */

// ---------------- scratch (device globals; no runtime allocation) ----------------
__device__ float g_y[MTOT*PLV];      // conv1 output, NHWC [pix][p]
__device__ float g_xm[MTOT*PLV];     // depthwise+bias output, NHWC
__device__ float g_xl[MTOT*PLV];     // relu(lower) output
__device__ float g_feat[MTOT*PLV];   // relu(xm+xr)
__device__ float g_w1t[CINV*PLV];    // conv1_w transposed [c][p]
__device__ float g_lwt[PLV*PLV];     // (unused; kept for template references)
__device__ float g_fwt[PLV*CINV];    // fc_w transposed [p][o]
__device__ float g_att[BTOT*PLV];
__device__ float g_pool_sum[BTOT*PLV];
__device__ int   g_pool_max[BTOT*PLV];

// ---------------- init: zero pools + transpose weights ----------------
__global__ void init_kernel(const float* __restrict__ w1,
                            const float* __restrict__ fw)
{
    int i = blockIdx.x * 256 + threadIdx.x;
    if (i < BTOT*PLV) { g_pool_sum[i] = 0.f; g_pool_max[i] = 0; }
    if (i < CINV*PLV) { int c = i / PLV, p = i % PLV; g_w1t[i] = w1[p*CINV + c]; }
    if (i < PLV*CINV) { int p = i / CINV, o = i % CINV; g_fwt[i] = fw[o*PLV + p]; }
}

// ------------- double-buffered tiled SIMT GEMM (128x128 tile, 8x8/thread) --------
// MODE 0: y = x @ w1t            (A = x, k-major layout; C = g_y, NHWC)
// MODE 2: out = (feat*att)@fwt+b (A = g_feat row-major scaled by g_att; C NCHW)
template<int KDIM, int MODE, int ALAYOUT>
__global__ __launch_bounds__(256, 2)
void gemm_kernel(const float* __restrict__ Aparam, const float* __restrict__ bias,
                 float* __restrict__ Cparam, int Ncols)
{
    const float* A  = (MODE==0) ? Aparam : (MODE==1) ? g_xm : g_feat;
    const float* Bt = (MODE==0) ? g_w1t  : (MODE==1) ? g_lwt : g_fwt;
    float*       C  = (MODE==0) ? g_y    : (MODE==1) ? g_xl  : Cparam;

    __shared__ float As[2][16][132];
    __shared__ float Bs[2][16][132];

    const int m0 = blockIdx.x * 128;
    const int n0 = blockIdx.y * 128;
    const int t  = threadIdx.x;
    const int tx = t & 15;
    const int ty = t >> 4;
    const int batch = m0 >> 12;

    float4 pa[2], pb[2];

#define LOAD_TILE(K0)                                                            \
    do {                                                                         \
        if (ALAYOUT == 0) {                                                      \
            _Pragma("unroll")                                                    \
            for (int r = 0; r < 2; r++) {                                        \
                const int idx = t + 256*r;                                       \
                const int ka = idx >> 5, mv = (idx & 31) << 2;                   \
                pa[r] = *(const float4*)(A + (size_t)batch*KDIM*HWV              \
                         + (size_t)((K0)+ka)*HWV + (m0 & (HWV-1)) + mv);         \
            }                                                                    \
        } else {                                                                 \
            _Pragma("unroll")                                                    \
            for (int r = 0; r < 2; r++) {                                        \
                const int idx = t + 256*r;                                       \
                const int ma = idx >> 2, kv = (idx & 3) << 2;                    \
                float4 v = *(const float4*)(A + (size_t)(m0+ma)*KDIM + (K0)+kv); \
                if (MODE == 2) {                                                 \
                    const float4 sc = *(const float4*)(g_att + batch*PLV + (K0)+kv); \
                    v.x *= sc.x; v.y *= sc.y; v.z *= sc.z; v.w *= sc.w;          \
                }                                                                \
                pa[r] = v;                                                       \
            }                                                                    \
        }                                                                        \
        _Pragma("unroll")                                                        \
        for (int r = 0; r < 2; r++) {                                            \
            const int idx = t + 256*r;                                           \
            const int kb = idx >> 5, nv = (idx & 31) << 2;                       \
            pb[r] = *(const float4*)(Bt + (size_t)((K0)+kb)*Ncols + n0 + nv);    \
        }                                                                        \
    } while (0)

#define STORE_TILE(BUF)                                                          \
    do {                                                                         \
        if (ALAYOUT == 0) {                                                      \
            _Pragma("unroll")                                                    \
            for (int r = 0; r < 2; r++) {                                        \
                const int idx = t + 256*r;                                       \
                const int ka = idx >> 5, mv = (idx & 31) << 2;                   \
                *(float4*)&As[BUF][ka][mv] = pa[r];                              \
            }                                                                    \
        } else {                                                                 \
            _Pragma("unroll")                                                    \
            for (int r = 0; r < 2; r++) {                                        \
                const int idx = t + 256*r;                                       \
                const int ma = idx >> 2, kv = (idx & 3) << 2;                    \
                As[BUF][kv+0][ma] = pa[r].x; As[BUF][kv+1][ma] = pa[r].y;        \
                As[BUF][kv+2][ma] = pa[r].z; As[BUF][kv+3][ma] = pa[r].w;        \
            }                                                                    \
        }                                                                        \
        _Pragma("unroll")                                                        \
        for (int r = 0; r < 2; r++) {                                            \
            const int idx = t + 256*r;                                           \
            const int kb = idx >> 5, nv = (idx & 31) << 2;                       \
            *(float4*)&Bs[BUF][kb][nv] = pb[r];                                  \
        }                                                                        \
    } while (0)

    float acc[8][8];
#pragma unroll
    for (int i = 0; i < 8; i++)
#pragma unroll
        for (int j = 0; j < 8; j++) acc[i][j] = 0.f;

    LOAD_TILE(0);
    STORE_TILE(0);
    __syncthreads();

    const int NK = KDIM / 16;
    int buf = 0;
#pragma unroll 1
    for (int it = 0; it < NK; it++) {
        if (it + 1 < NK) LOAD_TILE((it + 1) * 16);
#pragma unroll
        for (int k = 0; k < 16; k++) {
            float4 a0 = *(float4*)&As[buf][k][ty<<2];
            float4 a1 = *(float4*)&As[buf][k][64 + (ty<<2)];
            float4 b0 = *(float4*)&Bs[buf][k][tx<<2];
            float4 b1 = *(float4*)&Bs[buf][k][64 + (tx<<2)];
            float am[8] = {a0.x,a0.y,a0.z,a0.w,a1.x,a1.y,a1.z,a1.w};
            float bn[8] = {b0.x,b0.y,b0.z,b0.w,b1.x,b1.y,b1.z,b1.w};
#pragma unroll
            for (int i = 0; i < 8; i++)
#pragma unroll
                for (int j = 0; j < 8; j++)
                    acc[i][j] = fmaf(am[i], bn[j], acc[i][j]);
        }
        if (it + 1 < NK) {
            STORE_TILE(buf ^ 1);
            __syncthreads();
        }
        buf ^= 1;
    }
#undef LOAD_TILE
#undef STORE_TILE

    if (MODE != 2) {
#pragma unroll
        for (int i = 0; i < 8; i++) {
            const int mr = (i < 4) ? ((ty<<2) + i) : (64 + (ty<<2) + i - 4);
            const int m  = m0 + mr;
#pragma unroll
            for (int jj = 0; jj < 2; jj++) {
                float4 v;
                v.x = acc[i][jj*4+0]; v.y = acc[i][jj*4+1];
                v.z = acc[i][jj*4+2]; v.w = acc[i][jj*4+3];
                const int n = n0 + (tx<<2) + jj*64;
                if (MODE == 1) {
                    const float4 bb = *(const float4*)(bias + n);
                    v.x = fmaxf(v.x + bb.x, 0.f);
                    v.y = fmaxf(v.y + bb.y, 0.f);
                    v.z = fmaxf(v.z + bb.z, 0.f);
                    v.w = fmaxf(v.w + bb.w, 0.f);
                }
                *(float4*)&C[(size_t)m*Ncols + n] = v;
            }
        }
    } else {
        // stage per jj-half through smem so NCHW stores are coalesced
        float* st = &As[0][0][0];
        const int pixbase = m0 & (HWV - 1);
        const int lane = t & 31, chb = t >> 5;
#pragma unroll
        for (int jj = 0; jj < 2; jj++) {
            __syncthreads();
#pragma unroll
            for (int i = 0; i < 8; i++) {
                const int mr = (i < 4) ? ((ty<<2) + i) : (64 + (ty<<2) + i - 4);
#pragma unroll
                for (int q = 0; q < 4; q++) {
                    const int n = (tx<<2) + q + jj*64;
                    st[mr*65 + (tx<<2) + q] = acc[i][jj*4+q] + bias[n];
                }
            }
            __syncthreads();
#pragma unroll
            for (int cp = 0; cp < 8; cp++) {
                const int ch = chb + 8*cp;
#pragma unroll
                for (int pbk = 0; pbk < 4; pbk++) {
                    const int pix = pbk*32 + lane;
                    C[(size_t)(batch*CINV + jj*64 + ch)*HWV + pixbase + pix]
                        = st[pix*65 + ch];
                }
            }
        }
    }
}

// ------------- warp-MMA split-bf16 GEMM: xl = relu(xm @ lower_w^T + b) ------------
// mma.sync.m16n8k16 bf16, fp32 accum. D = Ah*Bh + Ah*Bl + Al*Bh.
// smem: 4 buffers [128 rows][72 bf16] (144B row stride -> ldmatrix conflict-free).
#define LM_ROWE 72
#define LM_OFSB (128*LM_ROWE*2)            /* 18432 B per buffer */
#define LM_SMEM (4*LM_OFSB)                /* 73728 B */

__device__ __forceinline__ uint32_t smem_u32(const void* p) {
    uint32_t a;
    asm("{ .reg .u64 tmp; cvta.to.shared.u64 tmp, %1; cvt.u32.u64 %0, tmp; }"
        : "=r"(a) : "l"(p));
    return a;
}
__device__ __forceinline__ void ldm_x4(uint32_t* r, uint32_t addr) {
    asm volatile("ldmatrix.sync.aligned.m8n8.x4.shared.b16 {%0,%1,%2,%3}, [%4];"
        : "=r"(r[0]), "=r"(r[1]), "=r"(r[2]), "=r"(r[3]) : "r"(addr));
}
__device__ __forceinline__ void mma_bf16(float* c, const uint32_t* a, const uint32_t* b) {
    asm volatile("mma.sync.aligned.m16n8k16.row.col.f32.bf16.bf16.f32 "
        "{%0,%1,%2,%3},{%4,%5,%6,%7},{%8,%9},{%0,%1,%2,%3};"
        : "+f"(c[0]), "+f"(c[1]), "+f"(c[2]), "+f"(c[3])
        : "r"(a[0]), "r"(a[1]), "r"(a[2]), "r"(a[3]), "r"(b[0]), "r"(b[1]));
}
__device__ __forceinline__ uint32_t pack_hi(float x, float y) {
    __nv_bfloat162 h; h.x = __float2bfloat16(x); h.y = __float2bfloat16(y);
    return *(uint32_t*)&h;
}
__device__ __forceinline__ uint32_t pack_lo(float x, float y) {
    __nv_bfloat162 h;
    h.x = __float2bfloat16(x - __bfloat162float(__float2bfloat16(x)));
    h.y = __float2bfloat16(y - __bfloat162float(__float2bfloat16(y)));
    return *(uint32_t*)&h;
}

__global__ __launch_bounds__(256)
void lower_mma_kernel(const float* __restrict__ lw, const float* __restrict__ bias)
{
    extern __shared__ char sm[];
    const uint32_t sbase = smem_u32(sm);

    const int t = threadIdx.x, lane = t & 31, wid = t >> 5;
    const int m0 = blockIdx.x * 128;
    const int n0 = blockIdx.y * 128;
    const int wm = (wid & 3) * 32;          // warp m-offset within tile
    const int wn = (wid >> 2) * 64;         // warp n-offset within tile

    float acc[2][8][4];
#pragma unroll
    for (int a = 0; a < 2; a++)
#pragma unroll
        for (int b = 0; b < 8; b++)
#pragma unroll
            for (int cdx = 0; cdx < 4; cdx++) acc[a][b][cdx] = 0.f;

#pragma unroll 1
    for (int c = 0; c < 4; c++) {
        const int k0 = c * 64;
        // ---- convert fp32 -> split bf16 into smem ----
#pragma unroll
        for (int i = 0; i < 8; i++) {
            const int idx = t + 256*i;
            const int row = idx >> 4;
            const int c4  = (idx & 15) << 2;
            const uint32_t off = (uint32_t)(row * (LM_ROWE*2) + c4 * 2);

            const float4 va = *(const float4*)(g_xm + (size_t)(m0+row)*PLV + k0 + c4);
            const float4 vb = *(const float4*)(lw   + (size_t)(n0+row)*PLV + k0 + c4);

            *(uint2*)(sm + 0*LM_OFSB + off) = make_uint2(pack_hi(va.x,va.y), pack_hi(va.z,va.w));
            *(uint2*)(sm + 1*LM_OFSB + off) = make_uint2(pack_lo(va.x,va.y), pack_lo(va.z,va.w));
            *(uint2*)(sm + 2*LM_OFSB + off) = make_uint2(pack_hi(vb.x,vb.y), pack_hi(vb.z,vb.w));
            *(uint2*)(sm + 3*LM_OFSB + off) = make_uint2(pack_lo(vb.x,vb.y), pack_lo(vb.z,vb.w));
        }
        __syncthreads();

        // ---- mma over 4 k16 sub-chunks ----
#pragma unroll
        for (int ks = 0; ks < 4; ks++) {
            uint32_t ah[2][4], al[2][4];
#pragma unroll
            for (int mf = 0; mf < 2; mf++) {
                const uint32_t r   = wm + mf*16 + (lane & 15);
                const uint32_t col = ks*16 + ((lane >> 4) << 3);
                const uint32_t o   = r * (LM_ROWE*2) + col * 2;
                ldm_x4(ah[mf], sbase + 0*LM_OFSB + o);
                ldm_x4(al[mf], sbase + 1*LM_OFSB + o);
            }
#pragma unroll
            for (int g = 0; g < 4; g++) {
                uint32_t bh[4], bl[4];
                const uint32_t nrow = wn + g*16 + (lane & 7) + (((lane >> 4) & 1) << 3);
                const uint32_t kcol = ks*16 + (((lane >> 3) & 1) << 3);
                const uint32_t o    = nrow * (LM_ROWE*2) + kcol * 2;
                ldm_x4(bh, sbase + 2*LM_OFSB + o);
                ldm_x4(bl, sbase + 3*LM_OFSB + o);
#pragma unroll
                for (int h = 0; h < 2; h++) {
                    const int nf = g*2 + h;
#pragma unroll
                    for (int mf = 0; mf < 2; mf++) {
                        mma_bf16(acc[mf][nf], ah[mf], &bh[h*2]);
                        mma_bf16(acc[mf][nf], ah[mf], &bl[h*2]);
                        mma_bf16(acc[mf][nf], al[mf], &bh[h*2]);
                    }
                }
            }
        }
        __syncthreads();
    }

    // ---- epilogue: bias + relu -> g_xl ----
#pragma unroll
    for (int mf = 0; mf < 2; mf++) {
        const int r0 = m0 + wm + mf*16 + (lane >> 2);
#pragma unroll
        for (int nf = 0; nf < 8; nf++) {
            const int col = n0 + wn + nf*8 + ((lane & 3) << 1);
            const float b0v = bias[col], b1v = bias[col+1];
            float2 v0, v1;
            v0.x = fmaxf(acc[mf][nf][0] + b0v, 0.f);
            v0.y = fmaxf(acc[mf][nf][1] + b1v, 0.f);
            v1.x = fmaxf(acc[mf][nf][2] + b0v, 0.f);
            v1.y = fmaxf(acc[mf][nf][3] + b1v, 0.f);
            *(float2*)&g_xl[(size_t)r0*PLV + col]       = v0;
            *(float2*)&g_xl[(size_t)(r0+8)*PLV + col]   = v1;
        }
    }
}

// ------------- depthwise 3x3 + bias, NHWC, rolling 3-column window ---------------
__global__ __launch_bounds__(256)
void dw_kernel(const float* __restrict__ w3, const float* __restrict__ b3)
{
    const int p = threadIdx.x;
    float wv[9];
#pragma unroll
    for (int j = 0; j < 9; j++) wv[j] = w3[p*9 + j];
    const float bb = b3[p];

    const int pix0 = blockIdx.x * 16;
    const int b = pix0 >> 12, hw = pix0 & 4095, h = hw >> 6, w0 = hw & 63;
    const size_t rowm = (h > 0)      ? ((size_t)((b<<12) + ((h-1)<<6)) * PLV + p) : 0;
    const size_t rowc = (size_t)((b<<12) + (h<<6)) * PLV + p;
    const size_t rowp = (h < HHV-1)  ? ((size_t)((b<<12) + ((h+1)<<6)) * PLV + p) : 0;
    const bool hm = (h > 0), hp = (h < HHV-1);

    float a0,a1,a2, c0,c1,c2;
    if (w0 > 0) {
        a0 = hm ? g_y[rowm + (size_t)(w0-1)*PLV] : 0.f;
        a1 =      g_y[rowc + (size_t)(w0-1)*PLV];
        a2 = hp ? g_y[rowp + (size_t)(w0-1)*PLV] : 0.f;
    } else { a0 = a1 = a2 = 0.f; }
    c0 = hm ? g_y[rowm + (size_t)w0*PLV] : 0.f;
    c1 =      g_y[rowc + (size_t)w0*PLV];
    c2 = hp ? g_y[rowp + (size_t)w0*PLV] : 0.f;

#pragma unroll
    for (int k = 0; k < 16; k++) {
        const int ww = w0 + k + 1;
        float n0v, n1v, n2v;
        if (ww < WWV) {
            n0v = hm ? g_y[rowm + (size_t)ww*PLV] : 0.f;
            n1v =      g_y[rowc + (size_t)ww*PLV];
            n2v = hp ? g_y[rowp + (size_t)ww*PLV] : 0.f;
        } else { n0v = n1v = n2v = 0.f; }

        float acc = bb;
        acc = fmaf(a0, wv[0], acc); acc = fmaf(c0, wv[1], acc); acc = fmaf(n0v, wv[2], acc);
        acc = fmaf(a1, wv[3], acc); acc = fmaf(c1, wv[4], acc); acc = fmaf(n1v, wv[5], acc);
        acc = fmaf(a2, wv[6], acc); acc = fmaf(c2, wv[7], acc); acc = fmaf(n2v, wv[8], acc);
        g_xm[(size_t)(pix0 + k)*PLV + p] = acc;

        a0 = c0; a1 = c1; a2 = c2;
        c0 = n0v; c1 = n1v; c2 = n2v;
    }
}

// ---------------- FAST EM: scalar path for r-uniform bases (one warp / pixel) -----
__global__ __launch_bounds__(512)
void em_fast(const float* __restrict__ binit)
{
    __shared__ float bsum[PLV];
    __shared__ int   bmx[PLV];
    const int t = threadIdx.x;
    if (t < PLV) { bsum[t] = 0.f; bmx[t] = 0; }
    __syncthreads();

    const int w = t >> 5, lane = t & 31;
    const int m = blockIdx.x * 16 + w;

    float bv = 1.f;
    if (lane < RRV) {
        const float v = binit[m*RRV + lane];
        bv = v / fmaxf(fabsf(v), 1e-12f);
    }
    const float b0 = __shfl_sync(0xffffffffu, bv, 0);
    const bool uni = __all_sync(0xffffffffu, (lane >= RRV) || (bv == b0));

    if (uni) {
        float b = b0;
        float x[8], cf[8];
        {
            const float4 v0 = *(const float4*)(g_xl + (size_t)m*PLV + lane*8);
            const float4 v1 = *(const float4*)(g_xl + (size_t)m*PLV + lane*8 + 4);
            x[0]=v0.x; x[1]=v0.y; x[2]=v0.z; x[3]=v0.w;
            x[4]=v1.x; x[5]=v1.y; x[6]=v1.z; x[7]=v1.w;
        }
#pragma unroll
        for (int j = 0; j < 8; j++) cf[j] = 0.0625f;

#pragma unroll
        for (int step = 0; step < STEPSV; step++) {
            float ps = 0.f, qs = 0.f;
#pragma unroll
            for (int j = 0; j < 8; j++) {
                const float tb  = cf[j] * b;
                const float den = fmaf(16.f*tb, b, EPSV);
                const float num = x[j] * b;
                cf[j] = cf[j] * num * __fdividef(1.f, den);
                ps = fmaf(x[j],  cf[j], ps);
                qs = fmaf(cf[j], cf[j], qs);
            }
#pragma unroll
            for (int off = 16; off > 0; off >>= 1) {
                ps += __shfl_xor_sync(0xffffffffu, ps, off);
                qs += __shfl_xor_sync(0xffffffffu, qs, off);
            }
            const float den = fmaf(16.f*b, qs, EPSV);
            b = b * ps * __fdividef(1.f, den);
        }
#pragma unroll
        for (int j = 0; j < 8; j++) {
            const float tb  = cf[j] * b;
            const float den = fmaf(16.f*tb, b, EPSV);
            const float num = x[j] * b;
            cf[j] = cf[j] * num * __fdividef(1.f, den);
        }
        const float4 m0v = *(const float4*)(g_xm + (size_t)m*PLV + lane*8);
        const float4 m1v = *(const float4*)(g_xm + (size_t)m*PLV + lane*8 + 4);
        const float xm8[8] = {m0v.x,m0v.y,m0v.z,m0v.w,m1v.x,m1v.y,m1v.z,m1v.w};
        float f[8];
#pragma unroll
        for (int j = 0; j < 8; j++) {
            f[j] = fmaxf(fmaf(16.f*b, cf[j], xm8[j]), 0.f);
            const int n = lane*8 + j;
            atomicAdd(&bsum[n], f[j]);
            atomicMax(&bmx[n], __float_as_int(f[j]));
        }
        float4 o0 = make_float4(f[0],f[1],f[2],f[3]);
        float4 o1 = make_float4(f[4],f[5],f[6],f[7]);
        *(float4*)(g_feat + (size_t)m*PLV + lane*8)     = o0;
        *(float4*)(g_feat + (size_t)m*PLV + lane*8 + 4) = o1;
    }
    __syncthreads();
    if (t < PLV) {
        const int bb = (blockIdx.x * 16) >> 12;
        atomicAdd(&g_pool_sum[bb*PLV + t], bsum[t]);
        atomicMax(&g_pool_max[bb*PLV + t], bmx[t]);
    }
}

// ---------------- GENERAL EM (fallback for non-uniform warps) ----------------
__global__ __launch_bounds__(256, 1)
void em_general(const float* __restrict__ binit)
{
    __shared__ float bsum[PLV];
    __shared__ int   bmx[PLV];
    const int t = threadIdx.x;
    bsum[t] = 0.f; bmx[t] = 0;
    __syncthreads();

    const int w = t >> 5, lane = t & 31;
    const int m = blockIdx.x * 8 + w;

    float b[RRV];
#pragma unroll
    for (int r = 0; r < RRV; r++) {
        const float v = binit[m*RRV + r];
        b[r] = v / fmaxf(fabsf(v), 1e-12f);
    }
    bool uni = true;
#pragma unroll
    for (int r = 1; r < RRV; r++) uni &= (b[r] == b[0]);

    bool did = false;
    if (!uni) {
        did = true;
        float x[8];
#pragma unroll
        for (int j = 0; j < 8; j++) x[j] = g_xl[(size_t)m*PLV + lane + 32*j];

        float cf[8][RRV];
#pragma unroll
        for (int j = 0; j < 8; j++) {
            const float xn = x[j];
            float tv[RRV]; float mx = -3.4e38f;
#pragma unroll
            for (int r = 0; r < RRV; r++) { tv[r] = xn * b[r]; mx = fmaxf(mx, tv[r]); }
            float s = 0.f;
#pragma unroll
            for (int r = 0; r < RRV; r++) { const float e = __expf(tv[r]-mx); cf[j][r]=e; s+=e; }
            const float inv = __fdividef(1.f, s);
#pragma unroll
            for (int r = 0; r < RRV; r++) cf[j][r] *= inv;
        }
        for (int step = 0; step < STEPSV; step++) {
#pragma unroll
            for (int j = 0; j < 8; j++) {
                float s = 0.f;
#pragma unroll
                for (int r = 0; r < RRV; r++) s = fmaf(cf[j][r], b[r], s);
                const float xn = x[j];
#pragma unroll
                for (int r = 0; r < RRV; r++) {
                    const float num = xn * b[r];
                    const float den = fmaf(s, b[r], EPSV);
                    cf[j][r] = cf[j][r] * num * __fdividef(1.f, den);
                }
            }
            float p[RRV], q[RRV];
#pragma unroll
            for (int r = 0; r < RRV; r++) { p[r]=0.f; q[r]=0.f; }
#pragma unroll
            for (int j = 0; j < 8; j++) {
                float sp = 0.f;
#pragma unroll
                for (int r = 0; r < RRV; r++) sp = fmaf(cf[j][r], b[r], sp);
                const float xn = x[j];
#pragma unroll
                for (int r = 0; r < RRV; r++) {
                    p[r] = fmaf(xn, cf[j][r], p[r]);
                    q[r] = fmaf(sp, cf[j][r], q[r]);
                }
            }
#pragma unroll
            for (int off = 16; off > 0; off >>= 1) {
#pragma unroll
                for (int r = 0; r < RRV; r++) {
                    p[r] += __shfl_xor_sync(0xffffffffu, p[r], off);
                    q[r] += __shfl_xor_sync(0xffffffffu, q[r], off);
                }
            }
#pragma unroll
            for (int r = 0; r < RRV; r++)
                b[r] = b[r] * p[r] * __fdividef(1.f, q[r] + EPSV);
        }
#pragma unroll
        for (int j = 0; j < 8; j++) {
            float s = 0.f;
#pragma unroll
            for (int r = 0; r < RRV; r++) s = fmaf(cf[j][r], b[r], s);
            const float xn = x[j];
#pragma unroll
            for (int r = 0; r < RRV; r++) {
                const float num = xn * b[r];
                const float den = fmaf(s, b[r], EPSV);
                cf[j][r] = cf[j][r] * num * __fdividef(1.f, den);
            }
        }
#pragma unroll
        for (int j = 0; j < 8; j++) {
            float xr = 0.f;
#pragma unroll
            for (int r = 0; r < RRV; r++) xr = fmaf(b[r], cf[j][r], xr);
            const int n = lane + 32*j;
            const float f = fmaxf(g_xm[(size_t)m*PLV + n] + xr, 0.f);
            g_feat[(size_t)m*PLV + n] = f;
            atomicAdd(&bsum[n], f);
            atomicMax(&bmx[n], __float_as_int(f));
        }
    }
    __syncthreads();
    if (__syncthreads_or(did)) {
        const int bb = (blockIdx.x * 8) >> 12;
        atomicAdd(&g_pool_sum[bb*PLV + t], bsum[t]);
        atomicMax(&g_pool_max[bb*PLV + t], bmx[t]);
    }
}

// ---------------- channel attention ----------------
__global__ __launch_bounds__(256)
void ca_kernel(const float* __restrict__ ca1, const float* __restrict__ ca2,
               float* __restrict__ out)
{
    const int b = blockIdx.x;
    const int t = threadIdx.x;
    __shared__ float sAvg[PLV], sMx[PLV], h1[ATTV];
    sAvg[t] = g_pool_sum[b*PLV + t] * (1.0f/(float)HWV);
    sMx[t]  = __int_as_float(g_pool_max[b*PLV + t]);
    __syncthreads();
    if (t < ATTV) {
        float a1 = 0.f, a2 = 0.f;
        for (int p = 0; p < PLV; p++) {
            const float wv = ca1[t*PLV + p];
            a1 = fmaf(wv, sAvg[p], a1);
            a2 = fmaf(wv, sMx[p],  a2);
        }
        h1[t] = fmaxf(a1, 0.f) + fmaxf(a2, 0.f);
    }
    __syncthreads();
    float v = 0.f;
    for (int a = 0; a < ATTV; a++) v = fmaf(h1[a], ca2[t*ATTV + a], v);
    const float att = __fdividef(1.f, 1.f + __expf(-v));
    g_att[b*PLV + t] = att;
    out[(size_t)BTOT*CINV*HWV + b*PLV + t] = att;
}

// ---------------- launch ----------------
extern "C" void kernel_launch(void* const* d_in, const int* in_sizes, int n_in,
                              void* d_out, int out_size)
{
    const float* x       = (const float*)d_in[0];
    const float* conv1_w = (const float*)d_in[1];
    const float* conv3_w = (const float*)d_in[2];
    const float* conv3_b = (const float*)d_in[3];
    const float* lower_w = (const float*)d_in[4];
    const float* lower_b = (const float*)d_in[5];
    const float* ca1_w   = (const float*)d_in[6];
    const float* ca2_w   = (const float*)d_in[7];
    const float* fc_w    = (const float*)d_in[8];
    const float* fc_b    = (const float*)d_in[9];
    const float* bases   = (const float*)d_in[10];
    float* out = (float*)d_out;

    static int smem_set = 0;
    if (!smem_set) {
        cudaFuncSetAttribute(lower_mma_kernel,
                             cudaFuncAttributeMaxDynamicSharedMemorySize, LM_SMEM);
        smem_set = 1;
    }

    init_kernel<<<256, 256>>>(conv1_w, fc_w);
    gemm_kernel<CINV, 0, 0><<<dim3(MTOT/128, PLV/128), 256>>>(x, nullptr, nullptr, PLV);
    dw_kernel<<<MTOT/16, 256>>>(conv3_w, conv3_b);
    lower_mma_kernel<<<dim3(MTOT/128, PLV/128), 256, LM_SMEM>>>(lower_w, lower_b);
    em_fast<<<MTOT/16, 512>>>(bases);
    em_general<<<MTOT/8, 256>>>(bases);
    ca_kernel<<<BTOT, 256>>>(ca1_w, ca2_w, out);
    gemm_kernel<PLV, 2, 1><<<dim3(MTOT/128, 1), 256>>>(nullptr, fc_b, out, CINV);
}

// round 8
// speedup vs baseline: 1.4377x; 1.1875x over previous
#include <cuda_runtime.h>
#include <cuda_bf16.h>
#include <math.h>
#include <stdint.h>

#define BTOT 4
#define CINV 128
#define HHV 64
#define WWV 64
#define PLV 256
#define ATTV 64
#define RRV 16
#define STEPSV 6
#define EPSV 1e-6f
#define MTOT (BTOT*HHV*WWV)   /* 16384 */
#define HWV (HHV*WWV)         /* 4096 */

// ---------------- scratch (device globals; no runtime allocation) ----------------
__device__ float g_y[MTOT*PLV];      // conv1 output, NHWC [pix][p]
__device__ float g_xm[MTOT*PLV];     // depthwise+bias output, NHWC
__device__ float g_xl[MTOT*PLV];     // relu(lower) output
__device__ float g_feat[MTOT*PLV];   // relu(xm+xr)
__device__ float g_att[BTOT*PLV];
__device__ float g_pool_sum[BTOT*PLV];
__device__ int   g_pool_max[BTOT*PLV];

// ---------------- MMA/ldmatrix helpers (mappings validated in round 7) ------------
__device__ __forceinline__ uint32_t smem_u32(const void* p) {
    uint32_t a;
    asm("{ .reg .u64 tmp; cvta.to.shared.u64 tmp, %1; cvt.u32.u64 %0, tmp; }"
        : "=r"(a) : "l"(p));
    return a;
}
__device__ __forceinline__ void ldm_x4(uint32_t* r, uint32_t addr) {
    asm volatile("ldmatrix.sync.aligned.m8n8.x4.shared.b16 {%0,%1,%2,%3}, [%4];"
        : "=r"(r[0]), "=r"(r[1]), "=r"(r[2]), "=r"(r[3]) : "r"(addr));
}
__device__ __forceinline__ void ldm_x4_t(uint32_t* r, uint32_t addr) {
    asm volatile("ldmatrix.sync.aligned.m8n8.x4.trans.shared.b16 {%0,%1,%2,%3}, [%4];"
        : "=r"(r[0]), "=r"(r[1]), "=r"(r[2]), "=r"(r[3]) : "r"(addr));
}
__device__ __forceinline__ void mma_bf16(float* c, const uint32_t* a, const uint32_t* b) {
    asm volatile("mma.sync.aligned.m16n8k16.row.col.f32.bf16.bf16.f32 "
        "{%0,%1,%2,%3},{%4,%5,%6,%7},{%8,%9},{%0,%1,%2,%3};"
        : "+f"(c[0]), "+f"(c[1]), "+f"(c[2]), "+f"(c[3])
        : "r"(a[0]), "r"(a[1]), "r"(a[2]), "r"(a[3]), "r"(b[0]), "r"(b[1]));
}
__device__ __forceinline__ uint32_t pack_hi(float x, float y) {
    __nv_bfloat162 h; h.x = __float2bfloat16(x); h.y = __float2bfloat16(y);
    return *(uint32_t*)&h;
}
__device__ __forceinline__ uint32_t pack_lo(float x, float y) {
    __nv_bfloat162 h;
    h.x = __float2bfloat16(x - __bfloat162float(__float2bfloat16(x)));
    h.y = __float2bfloat16(y - __bfloat162float(__float2bfloat16(y)));
    return *(uint32_t*)&h;
}

#define LM_ROWE 72
#define LM_OFSB (128*LM_ROWE*2)            /* 18432 B per [128][72] bf16 buffer */
#define LM_SMEM (4*LM_OFSB)                /* 73728 B */

// A-as-[k][m] buffers for conv1: 64 k-rows x 136 bf16 (272B stride)
#define C1_AROW 272
#define C1_AOFS (64*C1_AROW)               /* 17408 B */

// ---------------- init: zero pooling accumulators ----------------
__global__ void init_kernel()
{
    int i = blockIdx.x * 256 + threadIdx.x;
    if (i < BTOT*PLV) { g_pool_sum[i] = 0.f; g_pool_max[i] = 0; }
}

// ------------- conv1 MMA: y = x @ conv1_w^T (A [k][m] via ldmatrix.trans) ---------
__global__ __launch_bounds__(256)
void conv1_mma_kernel(const float* __restrict__ x, const float* __restrict__ w1)
{
    extern __shared__ char sm[];
    const uint32_t sbase = smem_u32(sm);
    char* pAH = sm;
    char* pAL = sm + C1_AOFS;
    char* pBH = sm + 2*C1_AOFS;
    char* pBL = sm + 2*C1_AOFS + LM_OFSB;
    const uint32_t oAH = 0, oAL = C1_AOFS, oBH = 2*C1_AOFS, oBL = 2*C1_AOFS + LM_OFSB;

    const int t = threadIdx.x, lane = t & 31, wid = t >> 5;
    const int m0 = blockIdx.x * 128;
    const int n0 = blockIdx.y * 128;
    const int batch = m0 >> 12;
    const int pix0 = m0 & (HWV - 1);
    const int wm = (wid & 3) * 32;
    const int wn = (wid >> 2) * 64;

    float acc[2][8][4];
#pragma unroll
    for (int a = 0; a < 2; a++)
#pragma unroll
        for (int b = 0; b < 8; b++)
#pragma unroll
            for (int q = 0; q < 4; q++) acc[a][b][q] = 0.f;

#pragma unroll 1
    for (int c = 0; c < 2; c++) {
        const int k0 = c * 64;
        // A convert: x[k][m] -> smem [64 k-rows][128 m], coalesced
#pragma unroll
        for (int i = 0; i < 8; i++) {
            const int idx = t + 256*i;
            const int row = idx >> 5;            // k (0..63)
            const int mc  = (idx & 31) << 2;     // m (0..124)
            const float4 v = *(const float4*)(x + (size_t)batch*CINV*HWV
                                              + (size_t)(k0+row)*HWV + pix0 + mc);
            const uint32_t off = (uint32_t)(row*C1_AROW + mc*2);
            *(uint2*)(pAH + off) = make_uint2(pack_hi(v.x,v.y), pack_hi(v.z,v.w));
            *(uint2*)(pAL + off) = make_uint2(pack_lo(v.x,v.y), pack_lo(v.z,v.w));
        }
        // B convert: conv1_w [n][k] rows n0..n0+127
#pragma unroll
        for (int i = 0; i < 8; i++) {
            const int idx = t + 256*i;
            const int row = idx >> 4;            // n (0..127)
            const int c4  = (idx & 15) << 2;     // k (0..60)
            const float4 v = *(const float4*)(w1 + (size_t)(n0+row)*CINV + k0 + c4);
            const uint32_t off = (uint32_t)(row*(LM_ROWE*2) + c4*2);
            *(uint2*)(pBH + off) = make_uint2(pack_hi(v.x,v.y), pack_hi(v.z,v.w));
            *(uint2*)(pBL + off) = make_uint2(pack_lo(v.x,v.y), pack_lo(v.z,v.w));
        }
        __syncthreads();

#pragma unroll
        for (int ks = 0; ks < 4; ks++) {
            uint32_t ah[2][4], al[2][4];
            const int q = lane >> 3;
            const uint32_t krow = ks*16 + ((q & 2) << 2) + (lane & 7);
#pragma unroll
            for (int mf = 0; mf < 2; mf++) {
                const uint32_t mc = wm + mf*16 + ((q & 1) << 3);
                const uint32_t o  = krow*C1_AROW + mc*2;
                ldm_x4_t(ah[mf], sbase + oAH + o);
                ldm_x4_t(al[mf], sbase + oAL + o);
            }
#pragma unroll
            for (int g = 0; g < 4; g++) {
                uint32_t bh[4], bl[4];
                const uint32_t nrow = wn + g*16 + (lane & 7) + (((lane >> 4) & 1) << 3);
                const uint32_t kcol = ks*16 + (((lane >> 3) & 1) << 3);
                const uint32_t o    = nrow*(LM_ROWE*2) + kcol*2;
                ldm_x4(bh, sbase + oBH + o);
                ldm_x4(bl, sbase + oBL + o);
#pragma unroll
                for (int h = 0; h < 2; h++) {
                    const int nf = g*2 + h;
#pragma unroll
                    for (int mf = 0; mf < 2; mf++) {
                        mma_bf16(acc[mf][nf], ah[mf], &bh[h*2]);
                        mma_bf16(acc[mf][nf], ah[mf], &bl[h*2]);
                        mma_bf16(acc[mf][nf], al[mf], &bh[h*2]);
                    }
                }
            }
        }
        __syncthreads();
    }

    // epilogue: g_y row-major
#pragma unroll
    for (int mf = 0; mf < 2; mf++) {
        const int r0 = m0 + wm + mf*16 + (lane >> 2);
#pragma unroll
        for (int nf = 0; nf < 8; nf++) {
            const int col = n0 + wn + nf*8 + ((lane & 3) << 1);
            float2 v0, v1;
            v0.x = acc[mf][nf][0]; v0.y = acc[mf][nf][1];
            v1.x = acc[mf][nf][2]; v1.y = acc[mf][nf][3];
            *(float2*)&g_y[(size_t)r0*PLV + col]     = v0;
            *(float2*)&g_y[(size_t)(r0+8)*PLV + col] = v1;
        }
    }
}

// ------------- lower MMA: xl = relu(xm @ lower_w^T + b) (round-7 proven) ----------
__global__ __launch_bounds__(256)
void lower_mma_kernel(const float* __restrict__ lw, const float* __restrict__ bias)
{
    extern __shared__ char sm[];
    const uint32_t sbase = smem_u32(sm);

    const int t = threadIdx.x, lane = t & 31, wid = t >> 5;
    const int m0 = blockIdx.x * 128;
    const int n0 = blockIdx.y * 128;
    const int wm = (wid & 3) * 32;
    const int wn = (wid >> 2) * 64;

    float acc[2][8][4];
#pragma unroll
    for (int a = 0; a < 2; a++)
#pragma unroll
        for (int b = 0; b < 8; b++)
#pragma unroll
            for (int q = 0; q < 4; q++) acc[a][b][q] = 0.f;

#pragma unroll 1
    for (int c = 0; c < 4; c++) {
        const int k0 = c * 64;
#pragma unroll
        for (int i = 0; i < 8; i++) {
            const int idx = t + 256*i;
            const int row = idx >> 4;
            const int c4  = (idx & 15) << 2;
            const uint32_t off = (uint32_t)(row * (LM_ROWE*2) + c4 * 2);

            const float4 va = *(const float4*)(g_xm + (size_t)(m0+row)*PLV + k0 + c4);
            const float4 vb = *(const float4*)(lw   + (size_t)(n0+row)*PLV + k0 + c4);

            *(uint2*)(sm + 0*LM_OFSB + off) = make_uint2(pack_hi(va.x,va.y), pack_hi(va.z,va.w));
            *(uint2*)(sm + 1*LM_OFSB + off) = make_uint2(pack_lo(va.x,va.y), pack_lo(va.z,va.w));
            *(uint2*)(sm + 2*LM_OFSB + off) = make_uint2(pack_hi(vb.x,vb.y), pack_hi(vb.z,vb.w));
            *(uint2*)(sm + 3*LM_OFSB + off) = make_uint2(pack_lo(vb.x,vb.y), pack_lo(vb.z,vb.w));
        }
        __syncthreads();

#pragma unroll
        for (int ks = 0; ks < 4; ks++) {
            uint32_t ah[2][4], al[2][4];
#pragma unroll
            for (int mf = 0; mf < 2; mf++) {
                const uint32_t r   = wm + mf*16 + (lane & 15);
                const uint32_t col = ks*16 + ((lane >> 4) << 3);
                const uint32_t o   = r * (LM_ROWE*2) + col * 2;
                ldm_x4(ah[mf], sbase + 0*LM_OFSB + o);
                ldm_x4(al[mf], sbase + 1*LM_OFSB + o);
            }
#pragma unroll
            for (int g = 0; g < 4; g++) {
                uint32_t bh[4], bl[4];
                const uint32_t nrow = wn + g*16 + (lane & 7) + (((lane >> 4) & 1) << 3);
                const uint32_t kcol = ks*16 + (((lane >> 3) & 1) << 3);
                const uint32_t o    = nrow * (LM_ROWE*2) + kcol * 2;
                ldm_x4(bh, sbase + 2*LM_OFSB + o);
                ldm_x4(bl, sbase + 3*LM_OFSB + o);
#pragma unroll
                for (int h = 0; h < 2; h++) {
                    const int nf = g*2 + h;
#pragma unroll
                    for (int mf = 0; mf < 2; mf++) {
                        mma_bf16(acc[mf][nf], ah[mf], &bh[h*2]);
                        mma_bf16(acc[mf][nf], ah[mf], &bl[h*2]);
                        mma_bf16(acc[mf][nf], al[mf], &bh[h*2]);
                    }
                }
            }
        }
        __syncthreads();
    }

#pragma unroll
    for (int mf = 0; mf < 2; mf++) {
        const int r0 = m0 + wm + mf*16 + (lane >> 2);
#pragma unroll
        for (int nf = 0; nf < 8; nf++) {
            const int col = n0 + wn + nf*8 + ((lane & 3) << 1);
            const float b0v = bias[col], b1v = bias[col+1];
            float2 v0, v1;
            v0.x = fmaxf(acc[mf][nf][0] + b0v, 0.f);
            v0.y = fmaxf(acc[mf][nf][1] + b1v, 0.f);
            v1.x = fmaxf(acc[mf][nf][2] + b0v, 0.f);
            v1.y = fmaxf(acc[mf][nf][3] + b1v, 0.f);
            *(float2*)&g_xl[(size_t)r0*PLV + col]     = v0;
            *(float2*)&g_xl[(size_t)(r0+8)*PLV + col] = v1;
        }
    }
}

// ------------- fc MMA: out = (feat*att) @ fc_w^T + b, NCHW epilogue --------------
// att folded into B during convert (block is single-batch; att scales the k dim).
__global__ __launch_bounds__(256)
void fc_mma_kernel(const float* __restrict__ fw, const float* __restrict__ bias,
                   float* __restrict__ out)
{
    extern __shared__ char sm[];
    const uint32_t sbase = smem_u32(sm);

    const int t = threadIdx.x, lane = t & 31, wid = t >> 5;
    const int m0 = blockIdx.x * 128;
    const int batch = m0 >> 12;
    const int pixbase = m0 & (HWV - 1);
    const int wm = (wid & 3) * 32;
    const int wn = (wid >> 2) * 64;

    float acc[2][8][4];
#pragma unroll
    for (int a = 0; a < 2; a++)
#pragma unroll
        for (int b = 0; b < 8; b++)
#pragma unroll
            for (int q = 0; q < 4; q++) acc[a][b][q] = 0.f;

#pragma unroll 1
    for (int c = 0; c < 4; c++) {
        const int k0 = c * 64;
#pragma unroll
        for (int i = 0; i < 8; i++) {
            const int idx = t + 256*i;
            const int row = idx >> 4;
            const int c4  = (idx & 15) << 2;
            const uint32_t off = (uint32_t)(row * (LM_ROWE*2) + c4 * 2);

            const float4 va = *(const float4*)(g_feat + (size_t)(m0+row)*PLV + k0 + c4);
            float4 vb = *(const float4*)(fw + (size_t)row*PLV + k0 + c4);   // n0 = 0
            const float4 at = *(const float4*)(g_att + batch*PLV + k0 + c4);
            vb.x *= at.x; vb.y *= at.y; vb.z *= at.z; vb.w *= at.w;

            *(uint2*)(sm + 0*LM_OFSB + off) = make_uint2(pack_hi(va.x,va.y), pack_hi(va.z,va.w));
            *(uint2*)(sm + 1*LM_OFSB + off) = make_uint2(pack_lo(va.x,va.y), pack_lo(va.z,va.w));
            *(uint2*)(sm + 2*LM_OFSB + off) = make_uint2(pack_hi(vb.x,vb.y), pack_hi(vb.z,vb.w));
            *(uint2*)(sm + 3*LM_OFSB + off) = make_uint2(pack_lo(vb.x,vb.y), pack_lo(vb.z,vb.w));
        }
        __syncthreads();

#pragma unroll
        for (int ks = 0; ks < 4; ks++) {
            uint32_t ah[2][4], al[2][4];
#pragma unroll
            for (int mf = 0; mf < 2; mf++) {
                const uint32_t r   = wm + mf*16 + (lane & 15);
                const uint32_t col = ks*16 + ((lane >> 4) << 3);
                const uint32_t o   = r * (LM_ROWE*2) + col * 2;
                ldm_x4(ah[mf], sbase + 0*LM_OFSB + o);
                ldm_x4(al[mf], sbase + 1*LM_OFSB + o);
            }
#pragma unroll
            for (int g = 0; g < 4; g++) {
                uint32_t bh[4], bl[4];
                const uint32_t nrow = wn + g*16 + (lane & 7) + (((lane >> 4) & 1) << 3);
                const uint32_t kcol = ks*16 + (((lane >> 3) & 1) << 3);
                const uint32_t o    = nrow * (LM_ROWE*2) + kcol * 2;
                ldm_x4(bh, sbase + 2*LM_OFSB + o);
                ldm_x4(bl, sbase + 3*LM_OFSB + o);
#pragma unroll
                for (int h = 0; h < 2; h++) {
                    const int nf = g*2 + h;
#pragma unroll
                    for (int mf = 0; mf < 2; mf++) {
                        mma_bf16(acc[mf][nf], ah[mf], &bh[h*2]);
                        mma_bf16(acc[mf][nf], ah[mf], &bl[h*2]);
                        mma_bf16(acc[mf][nf], al[mf], &bh[h*2]);
                    }
                }
            }
        }
        __syncthreads();
    }

    // NCHW epilogue via smem staging: st[pix 128][ch 128] stride 130
    float* st = (float*)sm;
#pragma unroll
    for (int mf = 0; mf < 2; mf++) {
        const int r0 = wm + mf*16 + (lane >> 2);
#pragma unroll
        for (int nf = 0; nf < 8; nf++) {
            const int col = wn + nf*8 + ((lane & 3) << 1);
            const float b0v = bias[col], b1v = bias[col+1];
            st[r0*130 + col]       = acc[mf][nf][0] + b0v;
            st[r0*130 + col + 1]   = acc[mf][nf][1] + b1v;
            st[(r0+8)*130 + col]     = acc[mf][nf][2] + b0v;
            st[(r0+8)*130 + col + 1] = acc[mf][nf][3] + b1v;
        }
    }
    __syncthreads();
    const int chb = t >> 5;
#pragma unroll
    for (int cp = 0; cp < 16; cp++) {
        const int ch = chb + 8*cp;
#pragma unroll
        for (int pbk = 0; pbk < 4; pbk++) {
            const int pix = pbk*32 + lane;
            out[(size_t)(batch*CINV + ch)*HWV + pixbase + pix] = st[pix*130 + ch];
        }
    }
}

// ------------- depthwise 3x3 + bias, NHWC, rolling 3-column window ---------------
__global__ __launch_bounds__(256)
void dw_kernel(const float* __restrict__ w3, const float* __restrict__ b3)
{
    const int p = threadIdx.x;
    float wv[9];
#pragma unroll
    for (int j = 0; j < 9; j++) wv[j] = w3[p*9 + j];
    const float bb = b3[p];

    const int pix0 = blockIdx.x * 16;
    const int b = pix0 >> 12, hw = pix0 & 4095, h = hw >> 6, w0 = hw & 63;
    const size_t rowm = (h > 0)      ? ((size_t)((b<<12) + ((h-1)<<6)) * PLV + p) : 0;
    const size_t rowc = (size_t)((b<<12) + (h<<6)) * PLV + p;
    const size_t rowp = (h < HHV-1)  ? ((size_t)((b<<12) + ((h+1)<<6)) * PLV + p) : 0;
    const bool hm = (h > 0), hp = (h < HHV-1);

    float a0,a1,a2, c0,c1,c2;
    if (w0 > 0) {
        a0 = hm ? g_y[rowm + (size_t)(w0-1)*PLV] : 0.f;
        a1 =      g_y[rowc + (size_t)(w0-1)*PLV];
        a2 = hp ? g_y[rowp + (size_t)(w0-1)*PLV] : 0.f;
    } else { a0 = a1 = a2 = 0.f; }
    c0 = hm ? g_y[rowm + (size_t)w0*PLV] : 0.f;
    c1 =      g_y[rowc + (size_t)w0*PLV];
    c2 = hp ? g_y[rowp + (size_t)w0*PLV] : 0.f;

#pragma unroll
    for (int k = 0; k < 16; k++) {
        const int ww = w0 + k + 1;
        float n0v, n1v, n2v;
        if (ww < WWV) {
            n0v = hm ? g_y[rowm + (size_t)ww*PLV] : 0.f;
            n1v =      g_y[rowc + (size_t)ww*PLV];
            n2v = hp ? g_y[rowp + (size_t)ww*PLV] : 0.f;
        } else { n0v = n1v = n2v = 0.f; }

        float acc = bb;
        acc = fmaf(a0, wv[0], acc); acc = fmaf(c0, wv[1], acc); acc = fmaf(n0v, wv[2], acc);
        acc = fmaf(a1, wv[3], acc); acc = fmaf(c1, wv[4], acc); acc = fmaf(n1v, wv[5], acc);
        acc = fmaf(a2, wv[6], acc); acc = fmaf(c2, wv[7], acc); acc = fmaf(n2v, wv[8], acc);
        g_xm[(size_t)(pix0 + k)*PLV + p] = acc;

        a0 = c0; a1 = c1; a2 = c2;
        c0 = n0v; c1 = n1v; c2 = n2v;
    }
}

// ---------------- FAST EM: scalar path for r-uniform bases (one warp / pixel) -----
__global__ __launch_bounds__(512)
void em_fast(const float* __restrict__ binit)
{
    __shared__ float bsum[PLV];
    __shared__ int   bmx[PLV];
    const int t = threadIdx.x;
    if (t < PLV) { bsum[t] = 0.f; bmx[t] = 0; }
    __syncthreads();

    const int w = t >> 5, lane = t & 31;
    const int m = blockIdx.x * 16 + w;

    float bv = 1.f;
    if (lane < RRV) {
        const float v = binit[m*RRV + lane];
        bv = v / fmaxf(fabsf(v), 1e-12f);
    }
    const float b0 = __shfl_sync(0xffffffffu, bv, 0);
    const bool uni = __all_sync(0xffffffffu, (lane >= RRV) || (bv == b0));

    if (uni) {
        float b = b0;
        float x[8], cf[8];
        {
            const float4 v0 = *(const float4*)(g_xl + (size_t)m*PLV + lane*8);
            const float4 v1 = *(const float4*)(g_xl + (size_t)m*PLV + lane*8 + 4);
            x[0]=v0.x; x[1]=v0.y; x[2]=v0.z; x[3]=v0.w;
            x[4]=v1.x; x[5]=v1.y; x[6]=v1.z; x[7]=v1.w;
        }
#pragma unroll
        for (int j = 0; j < 8; j++) cf[j] = 0.0625f;

#pragma unroll
        for (int step = 0; step < STEPSV; step++) {
            float ps = 0.f, qs = 0.f;
#pragma unroll
            for (int j = 0; j < 8; j++) {
                const float tb  = cf[j] * b;
                const float den = fmaf(16.f*tb, b, EPSV);
                const float num = x[j] * b;
                cf[j] = cf[j] * num * __fdividef(1.f, den);
                ps = fmaf(x[j],  cf[j], ps);
                qs = fmaf(cf[j], cf[j], qs);
            }
#pragma unroll
            for (int off = 16; off > 0; off >>= 1) {
                ps += __shfl_xor_sync(0xffffffffu, ps, off);
                qs += __shfl_xor_sync(0xffffffffu, qs, off);
            }
            const float den = fmaf(16.f*b, qs, EPSV);
            b = b * ps * __fdividef(1.f, den);
        }
#pragma unroll
        for (int j = 0; j < 8; j++) {
            const float tb  = cf[j] * b;
            const float den = fmaf(16.f*tb, b, EPSV);
            const float num = x[j] * b;
            cf[j] = cf[j] * num * __fdividef(1.f, den);
        }
        const float4 m0v = *(const float4*)(g_xm + (size_t)m*PLV + lane*8);
        const float4 m1v = *(const float4*)(g_xm + (size_t)m*PLV + lane*8 + 4);
        const float xm8[8] = {m0v.x,m0v.y,m0v.z,m0v.w,m1v.x,m1v.y,m1v.z,m1v.w};
        float f[8];
#pragma unroll
        for (int j = 0; j < 8; j++) {
            f[j] = fmaxf(fmaf(16.f*b, cf[j], xm8[j]), 0.f);
            const int n = lane*8 + j;
            atomicAdd(&bsum[n], f[j]);
            atomicMax(&bmx[n], __float_as_int(f[j]));
        }
        float4 o0 = make_float4(f[0],f[1],f[2],f[3]);
        float4 o1 = make_float4(f[4],f[5],f[6],f[7]);
        *(float4*)(g_feat + (size_t)m*PLV + lane*8)     = o0;
        *(float4*)(g_feat + (size_t)m*PLV + lane*8 + 4) = o1;
    }
    __syncthreads();
    if (t < PLV) {
        const int bb = (blockIdx.x * 16) >> 12;
        atomicAdd(&g_pool_sum[bb*PLV + t], bsum[t]);
        atomicMax(&g_pool_max[bb*PLV + t], bmx[t]);
    }
}

// ---------------- GENERAL EM (fallback for non-uniform warps) ----------------
__global__ __launch_bounds__(256, 1)
void em_general(const float* __restrict__ binit)
{
    __shared__ float bsum[PLV];
    __shared__ int   bmx[PLV];
    const int t = threadIdx.x;
    bsum[t] = 0.f; bmx[t] = 0;
    __syncthreads();

    const int w = t >> 5, lane = t & 31;
    const int m = blockIdx.x * 8 + w;

    float b[RRV];
#pragma unroll
    for (int r = 0; r < RRV; r++) {
        const float v = binit[m*RRV + r];
        b[r] = v / fmaxf(fabsf(v), 1e-12f);
    }
    bool uni = true;
#pragma unroll
    for (int r = 1; r < RRV; r++) uni &= (b[r] == b[0]);

    bool did = false;
    if (!uni) {
        did = true;
        float x[8];
#pragma unroll
        for (int j = 0; j < 8; j++) x[j] = g_xl[(size_t)m*PLV + lane + 32*j];

        float cf[8][RRV];
#pragma unroll
        for (int j = 0; j < 8; j++) {
            const float xn = x[j];
            float tv[RRV]; float mx = -3.4e38f;
#pragma unroll
            for (int r = 0; r < RRV; r++) { tv[r] = xn * b[r]; mx = fmaxf(mx, tv[r]); }
            float s = 0.f;
#pragma unroll
            for (int r = 0; r < RRV; r++) { const float e = __expf(tv[r]-mx); cf[j][r]=e; s+=e; }
            const float inv = __fdividef(1.f, s);
#pragma unroll
            for (int r = 0; r < RRV; r++) cf[j][r] *= inv;
        }
        for (int step = 0; step < STEPSV; step++) {
#pragma unroll
            for (int j = 0; j < 8; j++) {
                float s = 0.f;
#pragma unroll
                for (int r = 0; r < RRV; r++) s = fmaf(cf[j][r], b[r], s);
                const float xn = x[j];
#pragma unroll
                for (int r = 0; r < RRV; r++) {
                    const float num = xn * b[r];
                    const float den = fmaf(s, b[r], EPSV);
                    cf[j][r] = cf[j][r] * num * __fdividef(1.f, den);
                }
            }
            float p[RRV], q[RRV];
#pragma unroll
            for (int r = 0; r < RRV; r++) { p[r]=0.f; q[r]=0.f; }
#pragma unroll
            for (int j = 0; j < 8; j++) {
                float sp = 0.f;
#pragma unroll
                for (int r = 0; r < RRV; r++) sp = fmaf(cf[j][r], b[r], sp);
                const float xn = x[j];
#pragma unroll
                for (int r = 0; r < RRV; r++) {
                    p[r] = fmaf(xn, cf[j][r], p[r]);
                    q[r] = fmaf(sp, cf[j][r], q[r]);
                }
            }
#pragma unroll
            for (int off = 16; off > 0; off >>= 1) {
#pragma unroll
                for (int r = 0; r < RRV; r++) {
                    p[r] += __shfl_xor_sync(0xffffffffu, p[r], off);
                    q[r] += __shfl_xor_sync(0xffffffffu, q[r], off);
                }
            }
#pragma unroll
            for (int r = 0; r < RRV; r++)
                b[r] = b[r] * p[r] * __fdividef(1.f, q[r] + EPSV);
        }
#pragma unroll
        for (int j = 0; j < 8; j++) {
            float s = 0.f;
#pragma unroll
            for (int r = 0; r < RRV; r++) s = fmaf(cf[j][r], b[r], s);
            const float xn = x[j];
#pragma unroll
            for (int r = 0; r < RRV; r++) {
                const float num = xn * b[r];
                const float den = fmaf(s, b[r], EPSV);
                cf[j][r] = cf[j][r] * num * __fdividef(1.f, den);
            }
        }
#pragma unroll
        for (int j = 0; j < 8; j++) {
            float xr = 0.f;
#pragma unroll
            for (int r = 0; r < RRV; r++) xr = fmaf(b[r], cf[j][r], xr);
            const int n = lane + 32*j;
            const float f = fmaxf(g_xm[(size_t)m*PLV + n] + xr, 0.f);
            g_feat[(size_t)m*PLV + n] = f;
            atomicAdd(&bsum[n], f);
            atomicMax(&bmx[n], __float_as_int(f));
        }
    }
    __syncthreads();
    if (__syncthreads_or(did)) {
        const int bb = (blockIdx.x * 8) >> 12;
        atomicAdd(&g_pool_sum[bb*PLV + t], bsum[t]);
        atomicMax(&g_pool_max[bb*PLV + t], bmx[t]);
    }
}

// ---------------- channel attention ----------------
__global__ __launch_bounds__(256)
void ca_kernel(const float* __restrict__ ca1, const float* __restrict__ ca2,
               float* __restrict__ out)
{
    const int b = blockIdx.x;
    const int t = threadIdx.x;
    __shared__ float sAvg[PLV], sMx[PLV], h1[ATTV];
    sAvg[t] = g_pool_sum[b*PLV + t] * (1.0f/(float)HWV);
    sMx[t]  = __int_as_float(g_pool_max[b*PLV + t]);
    __syncthreads();
    if (t < ATTV) {
        float a1 = 0.f, a2 = 0.f;
        for (int p = 0; p < PLV; p++) {
            const float wv = ca1[t*PLV + p];
            a1 = fmaf(wv, sAvg[p], a1);
            a2 = fmaf(wv, sMx[p],  a2);
        }
        h1[t] = fmaxf(a1, 0.f) + fmaxf(a2, 0.f);
    }
    __syncthreads();
    float v = 0.f;
    for (int a = 0; a < ATTV; a++) v = fmaf(h1[a], ca2[t*ATTV + a], v);
    const float att = __fdividef(1.f, 1.f + __expf(-v));
    g_att[b*PLV + t] = att;
    out[(size_t)BTOT*CINV*HWV + b*PLV + t] = att;
}

// ---------------- launch ----------------
extern "C" void kernel_launch(void* const* d_in, const int* in_sizes, int n_in,
                              void* d_out, int out_size)
{
    const float* x       = (const float*)d_in[0];
    const float* conv1_w = (const float*)d_in[1];
    const float* conv3_w = (const float*)d_in[2];
    const float* conv3_b = (const float*)d_in[3];
    const float* lower_w = (const float*)d_in[4];
    const float* lower_b = (const float*)d_in[5];
    const float* ca1_w   = (const float*)d_in[6];
    const float* ca2_w   = (const float*)d_in[7];
    const float* fc_w    = (const float*)d_in[8];
    const float* fc_b    = (const float*)d_in[9];
    const float* bases   = (const float*)d_in[10];
    float* out = (float*)d_out;

    static int smem_set = 0;
    if (!smem_set) {
        cudaFuncSetAttribute(conv1_mma_kernel,
                             cudaFuncAttributeMaxDynamicSharedMemorySize, LM_SMEM);
        cudaFuncSetAttribute(lower_mma_kernel,
                             cudaFuncAttributeMaxDynamicSharedMemorySize, LM_SMEM);
        cudaFuncSetAttribute(fc_mma_kernel,
                             cudaFuncAttributeMaxDynamicSharedMemorySize, LM_SMEM);
        smem_set = 1;
    }

    init_kernel<<<4, 256>>>();
    conv1_mma_kernel<<<dim3(MTOT/128, PLV/128), 256, LM_SMEM>>>(x, conv1_w);
    dw_kernel<<<MTOT/16, 256>>>(conv3_w, conv3_b);
    lower_mma_kernel<<<dim3(MTOT/128, PLV/128), 256, LM_SMEM>>>(lower_w, lower_b);
    em_fast<<<MTOT/16, 512>>>(bases);
    em_general<<<MTOT/8, 256>>>(bases);
    ca_kernel<<<BTOT, 256>>>(ca1_w, ca2_w, out);
    fc_mma_kernel<<<MTOT/128, 256, LM_SMEM>>>(fc_w, fc_b, out);
}

// round 9
// speedup vs baseline: 1.6680x; 1.1602x over previous
#include <cuda_runtime.h>
#include <cuda_bf16.h>
#include <math.h>
#include <stdint.h>

#define BTOT 4
#define CINV 128
#define HHV 64
#define WWV 64
#define PLV 256
#define ATTV 64
#define RRV 16
#define STEPSV 6
#define EPSV 1e-6f
#define MTOT (BTOT*HHV*WWV)   /* 16384 */
#define HWV (HHV*WWV)         /* 4096 */

// ---------------- scratch (device globals; no runtime allocation) ----------------
__device__ float g_y[MTOT*PLV];        // conv1 output, NHWC
__device__ float g_xm[MTOT*PLV];       // depthwise+bias output, NHWC fp32
__device__ float g_xl[MTOT*PLV];       // relu(lower) output
__device__ __nv_bfloat16 g_xmh[MTOT*PLV], g_xml[MTOT*PLV];     // xm split
__device__ __nv_bfloat16 g_feath[MTOT*PLV], g_featl[MTOT*PLV]; // feat split
__device__ __nv_bfloat16 g_lwh[PLV*PLV], g_lwl[PLV*PLV];       // lower_w split
__device__ __nv_bfloat16 g_fwbh[BTOT*CINV*PLV], g_fwbl[BTOT*CINV*PLV]; // fc_w*att split
__device__ float g_att[BTOT*PLV];
__device__ float g_pool_sum[BTOT*PLV];
__device__ int   g_pool_max[BTOT*PLV];
__device__ int   g_nonuni;

// ---------------- MMA/ldmatrix helpers (mappings validated rounds 7-8) ------------
__device__ __forceinline__ uint32_t smem_u32(const void* p) {
    uint32_t a;
    asm("{ .reg .u64 tmp; cvta.to.shared.u64 tmp, %1; cvt.u32.u64 %0, tmp; }"
        : "=r"(a) : "l"(p));
    return a;
}
__device__ __forceinline__ void ldm_x4(uint32_t* r, uint32_t addr) {
    asm volatile("ldmatrix.sync.aligned.m8n8.x4.shared.b16 {%0,%1,%2,%3}, [%4];"
        : "=r"(r[0]), "=r"(r[1]), "=r"(r[2]), "=r"(r[3]) : "r"(addr));
}
__device__ __forceinline__ void ldm_x4_t(uint32_t* r, uint32_t addr) {
    asm volatile("ldmatrix.sync.aligned.m8n8.x4.trans.shared.b16 {%0,%1,%2,%3}, [%4];"
        : "=r"(r[0]), "=r"(r[1]), "=r"(r[2]), "=r"(r[3]) : "r"(addr));
}
__device__ __forceinline__ void mma_bf16(float* c, const uint32_t* a, const uint32_t* b) {
    asm volatile("mma.sync.aligned.m16n8k16.row.col.f32.bf16.bf16.f32 "
        "{%0,%1,%2,%3},{%4,%5,%6,%7},{%8,%9},{%0,%1,%2,%3};"
        : "+f"(c[0]), "+f"(c[1]), "+f"(c[2]), "+f"(c[3])
        : "r"(a[0]), "r"(a[1]), "r"(a[2]), "r"(a[3]), "r"(b[0]), "r"(b[1]));
}
__device__ __forceinline__ uint32_t pack_hi(float x, float y) {
    __nv_bfloat162 h; h.x = __float2bfloat16(x); h.y = __float2bfloat16(y);
    return *(uint32_t*)&h;
}
__device__ __forceinline__ uint32_t pack_lo(float x, float y) {
    __nv_bfloat162 h;
    h.x = __float2bfloat16(x - __bfloat162float(__float2bfloat16(x)));
    h.y = __float2bfloat16(y - __bfloat162float(__float2bfloat16(y)));
    return *(uint32_t*)&h;
}
#define CP16(d, s) \
    asm volatile("cp.async.ca.shared.global [%0], [%1], 16;" :: "r"(d), "l"(s))

#define LM_ROWE 72
#define LM_OFSB (128*LM_ROWE*2)            /* 18432 B per [128][72] bf16 buffer */
#define PIPE_STAGE (4*LM_OFSB)             /* 73728 B */
#define PIPE_SMEM  (2*PIPE_STAGE)          /* 147456 B */
#define LM_SMEM (4*LM_OFSB)                /* conv1 (single-stage) */

#define C1_AROW 272
#define C1_AOFS (64*C1_AROW)

// ---------------- init: zero pools/flag + split lower_w ----------------
__global__ void init_kernel(const float* __restrict__ lw)
{
    int i = blockIdx.x * 256 + threadIdx.x;     // grid 256 -> 65536
    if (i == 0) g_nonuni = 0;
    if (i < BTOT*PLV) { g_pool_sum[i] = 0.f; g_pool_max[i] = 0; }
    if (i < PLV*PLV) {
        const float v = lw[i];
        const __nv_bfloat16 h = __float2bfloat16(v);
        g_lwh[i] = h;
        g_lwl[i] = __float2bfloat16(v - __bfloat162float(h));
    }
}

// ------------- conv1 MMA (round-8 proven, unchanged) ------------------------------
__global__ __launch_bounds__(256)
void conv1_mma_kernel(const float* __restrict__ x, const float* __restrict__ w1)
{
    extern __shared__ char sm[];
    const uint32_t sbase = smem_u32(sm);
    char* pAH = sm;
    char* pAL = sm + C1_AOFS;
    char* pBH = sm + 2*C1_AOFS;
    char* pBL = sm + 2*C1_AOFS + LM_OFSB;
    const uint32_t oAH = 0, oAL = C1_AOFS, oBH = 2*C1_AOFS, oBL = 2*C1_AOFS + LM_OFSB;

    const int t = threadIdx.x, lane = t & 31, wid = t >> 5;
    const int m0 = blockIdx.x * 128;
    const int n0 = blockIdx.y * 128;
    const int batch = m0 >> 12;
    const int pix0 = m0 & (HWV - 1);
    const int wm = (wid & 3) * 32;
    const int wn = (wid >> 2) * 64;

    float acc[2][8][4];
#pragma unroll
    for (int a = 0; a < 2; a++)
#pragma unroll
        for (int b = 0; b < 8; b++)
#pragma unroll
            for (int q = 0; q < 4; q++) acc[a][b][q] = 0.f;

#pragma unroll 1
    for (int c = 0; c < 2; c++) {
        const int k0 = c * 64;
#pragma unroll
        for (int i = 0; i < 8; i++) {
            const int idx = t + 256*i;
            const int row = idx >> 5;
            const int mc  = (idx & 31) << 2;
            const float4 v = *(const float4*)(x + (size_t)batch*CINV*HWV
                                              + (size_t)(k0+row)*HWV + pix0 + mc);
            const uint32_t off = (uint32_t)(row*C1_AROW + mc*2);
            *(uint2*)(pAH + off) = make_uint2(pack_hi(v.x,v.y), pack_hi(v.z,v.w));
            *(uint2*)(pAL + off) = make_uint2(pack_lo(v.x,v.y), pack_lo(v.z,v.w));
        }
#pragma unroll
        for (int i = 0; i < 8; i++) {
            const int idx = t + 256*i;
            const int row = idx >> 4;
            const int c4  = (idx & 15) << 2;
            const float4 v = *(const float4*)(w1 + (size_t)(n0+row)*CINV + k0 + c4);
            const uint32_t off = (uint32_t)(row*(LM_ROWE*2) + c4*2);
            *(uint2*)(pBH + off) = make_uint2(pack_hi(v.x,v.y), pack_hi(v.z,v.w));
            *(uint2*)(pBL + off) = make_uint2(pack_lo(v.x,v.y), pack_lo(v.z,v.w));
        }
        __syncthreads();

#pragma unroll
        for (int ks = 0; ks < 4; ks++) {
            uint32_t ah[2][4], al[2][4];
            const int q = lane >> 3;
            const uint32_t krow = ks*16 + ((q & 2) << 2) + (lane & 7);
#pragma unroll
            for (int mf = 0; mf < 2; mf++) {
                const uint32_t mc = wm + mf*16 + ((q & 1) << 3);
                const uint32_t o  = krow*C1_AROW + mc*2;
                ldm_x4_t(ah[mf], sbase + oAH + o);
                ldm_x4_t(al[mf], sbase + oAL + o);
            }
#pragma unroll
            for (int g = 0; g < 4; g++) {
                uint32_t bh[4], bl[4];
                const uint32_t nrow = wn + g*16 + (lane & 7) + (((lane >> 4) & 1) << 3);
                const uint32_t kcol = ks*16 + (((lane >> 3) & 1) << 3);
                const uint32_t o    = nrow*(LM_ROWE*2) + kcol*2;
                ldm_x4(bh, sbase + oBH + o);
                ldm_x4(bl, sbase + oBL + o);
#pragma unroll
                for (int h = 0; h < 2; h++) {
                    const int nf = g*2 + h;
#pragma unroll
                    for (int mf = 0; mf < 2; mf++) {
                        mma_bf16(acc[mf][nf], ah[mf], &bh[h*2]);
                        mma_bf16(acc[mf][nf], ah[mf], &bl[h*2]);
                        mma_bf16(acc[mf][nf], al[mf], &bh[h*2]);
                    }
                }
            }
        }
        __syncthreads();
    }

#pragma unroll
    for (int mf = 0; mf < 2; mf++) {
        const int r0 = m0 + wm + mf*16 + (lane >> 2);
#pragma unroll
        for (int nf = 0; nf < 8; nf++) {
            const int col = n0 + wn + nf*8 + ((lane & 3) << 1);
            float2 v0, v1;
            v0.x = acc[mf][nf][0]; v0.y = acc[mf][nf][1];
            v1.x = acc[mf][nf][2]; v1.y = acc[mf][nf][3];
            *(float2*)&g_y[(size_t)r0*PLV + col]     = v0;
            *(float2*)&g_y[(size_t)(r0+8)*PLV + col] = v1;
        }
    }
}

// ------------- pipelined MMA (cp.async double-buffered, pre-split bf16) -----------
// MODE 1: xl = relu(A@B^T + bias)   A=g_xmh/l rows m0, B=g_lwh/l rows n0
// MODE 2: out = A@B^T + bias, NCHW  A=g_feath/l rows m0, B=g_fwbh/l rows batch*128
template<int MODE>
__global__ __launch_bounds__(256)
void mma_pipe_kernel(const __nv_bfloat16* __restrict__ Ah, const __nv_bfloat16* __restrict__ Al,
                     const __nv_bfloat16* __restrict__ Bh, const __nv_bfloat16* __restrict__ Bl,
                     const float* __restrict__ bias, float* __restrict__ outp)
{
    extern __shared__ char sm[];
    const uint32_t sbase = smem_u32(sm);

    const int t = threadIdx.x, lane = t & 31, wid = t >> 5;
    const int m0 = blockIdx.x * 128;
    const int n0 = (MODE == 1) ? blockIdx.y * 128 : 0;
    const int batch = m0 >> 12;
    const int brow0 = (MODE == 1) ? n0 : batch * 128;
    const int wm = (wid & 3) * 32;
    const int wn = (wid >> 2) * 64;

#define PREFETCH(STG, CC) do {                                                   \
        const int _k0 = (CC) * 64;                                               \
        _Pragma("unroll")                                                        \
        for (int _a = 0; _a < 4; _a++) {                                         \
            const __nv_bfloat16* _src = (_a==0)?Ah:(_a==1)?Al:(_a==2)?Bh:Bl;     \
            const int _rb = (_a < 2) ? m0 : brow0;                               \
            _Pragma("unroll")                                                    \
            for (int _ii = 0; _ii < 4; _ii++) {                                  \
                const int _j = t + 256*_ii;                                      \
                const int _row = _j >> 3, _seg = _j & 7;                         \
                const uint32_t _d = sbase + (STG)*PIPE_STAGE + _a*LM_OFSB        \
                                    + _row*(LM_ROWE*2) + _seg*16;                \
                CP16(_d, _src + (size_t)(_rb+_row)*PLV + _k0 + _seg*8);          \
            }                                                                    \
        }                                                                        \
        asm volatile("cp.async.commit_group;");                                  \
    } while (0)

    float acc[2][8][4];
#pragma unroll
    for (int a = 0; a < 2; a++)
#pragma unroll
        for (int b = 0; b < 8; b++)
#pragma unroll
            for (int q = 0; q < 4; q++) acc[a][b][q] = 0.f;

    PREFETCH(0, 0);

#pragma unroll 1
    for (int c = 0; c < 4; c++) {
        if (c < 3) {
            PREFETCH((c + 1) & 1, c + 1);
            asm volatile("cp.async.wait_group 1;");
        } else {
            asm volatile("cp.async.wait_group 0;");
        }
        __syncthreads();
        const uint32_t sb = sbase + (c & 1) * PIPE_STAGE;

#pragma unroll
        for (int ks = 0; ks < 4; ks++) {
            uint32_t ah[2][4], al[2][4];
#pragma unroll
            for (int mf = 0; mf < 2; mf++) {
                const uint32_t r   = wm + mf*16 + (lane & 15);
                const uint32_t col = ks*16 + ((lane >> 4) << 3);
                const uint32_t o   = r * (LM_ROWE*2) + col * 2;
                ldm_x4(ah[mf], sb + 0*LM_OFSB + o);
                ldm_x4(al[mf], sb + 1*LM_OFSB + o);
            }
#pragma unroll
            for (int g = 0; g < 4; g++) {
                uint32_t bh[4], bl[4];
                const uint32_t nrow = wn + g*16 + (lane & 7) + (((lane >> 4) & 1) << 3);
                const uint32_t kcol = ks*16 + (((lane >> 3) & 1) << 3);
                const uint32_t o    = nrow * (LM_ROWE*2) + kcol * 2;
                ldm_x4(bh, sb + 2*LM_OFSB + o);
                ldm_x4(bl, sb + 3*LM_OFSB + o);
#pragma unroll
                for (int h = 0; h < 2; h++) {
                    const int nf = g*2 + h;
#pragma unroll
                    for (int mf = 0; mf < 2; mf++) {
                        mma_bf16(acc[mf][nf], ah[mf], &bh[h*2]);
                        mma_bf16(acc[mf][nf], ah[mf], &bl[h*2]);
                        mma_bf16(acc[mf][nf], al[mf], &bh[h*2]);
                    }
                }
            }
        }
        __syncthreads();
    }
#undef PREFETCH

    if (MODE == 1) {
#pragma unroll
        for (int mf = 0; mf < 2; mf++) {
            const int r0 = m0 + wm + mf*16 + (lane >> 2);
#pragma unroll
            for (int nf = 0; nf < 8; nf++) {
                const int col = n0 + wn + nf*8 + ((lane & 3) << 1);
                const float b0v = bias[col], b1v = bias[col+1];
                float2 v0, v1;
                v0.x = fmaxf(acc[mf][nf][0] + b0v, 0.f);
                v0.y = fmaxf(acc[mf][nf][1] + b1v, 0.f);
                v1.x = fmaxf(acc[mf][nf][2] + b0v, 0.f);
                v1.y = fmaxf(acc[mf][nf][3] + b1v, 0.f);
                *(float2*)&g_xl[(size_t)r0*PLV + col]     = v0;
                *(float2*)&g_xl[(size_t)(r0+8)*PLV + col] = v1;
            }
        }
    } else {
        // NCHW epilogue via smem staging: st[pix 128][ch 128] stride 130
        float* st = (float*)sm;
        const int pixbase = m0 & (HWV - 1);
#pragma unroll
        for (int mf = 0; mf < 2; mf++) {
            const int r0 = wm + mf*16 + (lane >> 2);
#pragma unroll
            for (int nf = 0; nf < 8; nf++) {
                const int col = wn + nf*8 + ((lane & 3) << 1);
                const float b0v = bias[col], b1v = bias[col+1];
                st[r0*130 + col]         = acc[mf][nf][0] + b0v;
                st[r0*130 + col + 1]     = acc[mf][nf][1] + b1v;
                st[(r0+8)*130 + col]     = acc[mf][nf][2] + b0v;
                st[(r0+8)*130 + col + 1] = acc[mf][nf][3] + b1v;
            }
        }
        __syncthreads();
        const int chb = t >> 5;
#pragma unroll
        for (int cp = 0; cp < 16; cp++) {
            const int ch = chb + 8*cp;
#pragma unroll
            for (int pbk = 0; pbk < 4; pbk++) {
                const int pix = pbk*32 + lane;
                outp[(size_t)(batch*CINV + ch)*HWV + pixbase + pix] = st[pix*130 + ch];
            }
        }
    }
}

// ------------- depthwise 3x3 + bias, NHWC; writes fp32 + split bf16 ---------------
__global__ __launch_bounds__(256)
void dw_kernel(const float* __restrict__ w3, const float* __restrict__ b3)
{
    const int p = threadIdx.x;
    float wv[9];
#pragma unroll
    for (int j = 0; j < 9; j++) wv[j] = w3[p*9 + j];
    const float bb = b3[p];

    const int pix0 = blockIdx.x * 16;
    const int b = pix0 >> 12, hw = pix0 & 4095, h = hw >> 6, w0 = hw & 63;
    const size_t rowm = (h > 0)      ? ((size_t)((b<<12) + ((h-1)<<6)) * PLV + p) : 0;
    const size_t rowc = (size_t)((b<<12) + (h<<6)) * PLV + p;
    const size_t rowp = (h < HHV-1)  ? ((size_t)((b<<12) + ((h+1)<<6)) * PLV + p) : 0;
    const bool hm = (h > 0), hp = (h < HHV-1);

    float a0,a1,a2, c0,c1,c2;
    if (w0 > 0) {
        a0 = hm ? g_y[rowm + (size_t)(w0-1)*PLV] : 0.f;
        a1 =      g_y[rowc + (size_t)(w0-1)*PLV];
        a2 = hp ? g_y[rowp + (size_t)(w0-1)*PLV] : 0.f;
    } else { a0 = a1 = a2 = 0.f; }
    c0 = hm ? g_y[rowm + (size_t)w0*PLV] : 0.f;
    c1 =      g_y[rowc + (size_t)w0*PLV];
    c2 = hp ? g_y[rowp + (size_t)w0*PLV] : 0.f;

#pragma unroll
    for (int k = 0; k < 16; k++) {
        const int ww = w0 + k + 1;
        float n0v, n1v, n2v;
        if (ww < WWV) {
            n0v = hm ? g_y[rowm + (size_t)ww*PLV] : 0.f;
            n1v =      g_y[rowc + (size_t)ww*PLV];
            n2v = hp ? g_y[rowp + (size_t)ww*PLV] : 0.f;
        } else { n0v = n1v = n2v = 0.f; }

        float acc = bb;
        acc = fmaf(a0, wv[0], acc); acc = fmaf(c0, wv[1], acc); acc = fmaf(n0v, wv[2], acc);
        acc = fmaf(a1, wv[3], acc); acc = fmaf(c1, wv[4], acc); acc = fmaf(n1v, wv[5], acc);
        acc = fmaf(a2, wv[6], acc); acc = fmaf(c2, wv[7], acc); acc = fmaf(n2v, wv[8], acc);
        const size_t o = (size_t)(pix0 + k)*PLV + p;
        g_xm[o] = acc;
        const __nv_bfloat16 hi = __float2bfloat16(acc);
        g_xmh[o] = hi;
        g_xml[o] = __float2bfloat16(acc - __bfloat162float(hi));

        a0 = c0; a1 = c1; a2 = c2;
        c0 = n0v; c1 = n1v; c2 = n2v;
    }
}

// ---------------- FAST EM (writes feat as split bf16) ----------------
__global__ __launch_bounds__(512)
void em_fast(const float* __restrict__ binit)
{
    __shared__ float bsum[PLV];
    __shared__ int   bmx[PLV];
    const int t = threadIdx.x;
    if (t < PLV) { bsum[t] = 0.f; bmx[t] = 0; }
    __syncthreads();

    const int w = t >> 5, lane = t & 31;
    const int m = blockIdx.x * 16 + w;

    float bv = 1.f;
    if (lane < RRV) {
        const float v = binit[m*RRV + lane];
        bv = v / fmaxf(fabsf(v), 1e-12f);
    }
    const float b0 = __shfl_sync(0xffffffffu, bv, 0);
    const bool uni = __all_sync(0xffffffffu, (lane >= RRV) || (bv == b0));

    if (uni) {
        float b = b0;
        float x[8], cf[8];
        {
            const float4 v0 = *(const float4*)(g_xl + (size_t)m*PLV + lane*8);
            const float4 v1 = *(const float4*)(g_xl + (size_t)m*PLV + lane*8 + 4);
            x[0]=v0.x; x[1]=v0.y; x[2]=v0.z; x[3]=v0.w;
            x[4]=v1.x; x[5]=v1.y; x[6]=v1.z; x[7]=v1.w;
        }
#pragma unroll
        for (int j = 0; j < 8; j++) cf[j] = 0.0625f;

#pragma unroll
        for (int step = 0; step < STEPSV; step++) {
            float ps = 0.f, qs = 0.f;
#pragma unroll
            for (int j = 0; j < 8; j++) {
                const float tb  = cf[j] * b;
                const float den = fmaf(16.f*tb, b, EPSV);
                const float num = x[j] * b;
                cf[j] = cf[j] * num * __fdividef(1.f, den);
                ps = fmaf(x[j],  cf[j], ps);
                qs = fmaf(cf[j], cf[j], qs);
            }
#pragma unroll
            for (int off = 16; off > 0; off >>= 1) {
                ps += __shfl_xor_sync(0xffffffffu, ps, off);
                qs += __shfl_xor_sync(0xffffffffu, qs, off);
            }
            const float den = fmaf(16.f*b, qs, EPSV);
            b = b * ps * __fdividef(1.f, den);
        }
#pragma unroll
        for (int j = 0; j < 8; j++) {
            const float tb  = cf[j] * b;
            const float den = fmaf(16.f*tb, b, EPSV);
            const float num = x[j] * b;
            cf[j] = cf[j] * num * __fdividef(1.f, den);
        }
        const float4 m0v = *(const float4*)(g_xm + (size_t)m*PLV + lane*8);
        const float4 m1v = *(const float4*)(g_xm + (size_t)m*PLV + lane*8 + 4);
        const float xm8[8] = {m0v.x,m0v.y,m0v.z,m0v.w,m1v.x,m1v.y,m1v.z,m1v.w};
        float f[8];
#pragma unroll
        for (int j = 0; j < 8; j++) {
            f[j] = fmaxf(fmaf(16.f*b, cf[j], xm8[j]), 0.f);
            const int n = lane*8 + j;
            atomicAdd(&bsum[n], f[j]);
            atomicMax(&bmx[n], __float_as_int(f[j]));
        }
        uint4 hi, lo;
        hi.x = pack_hi(f[0],f[1]); hi.y = pack_hi(f[2],f[3]);
        hi.z = pack_hi(f[4],f[5]); hi.w = pack_hi(f[6],f[7]);
        lo.x = pack_lo(f[0],f[1]); lo.y = pack_lo(f[2],f[3]);
        lo.z = pack_lo(f[4],f[5]); lo.w = pack_lo(f[6],f[7]);
        *(uint4*)&g_feath[(size_t)m*PLV + lane*8] = hi;
        *(uint4*)&g_featl[(size_t)m*PLV + lane*8] = lo;
    } else if (lane == 0) {
        g_nonuni = 1;
    }
    __syncthreads();
    if (t < PLV) {
        const int bb = (blockIdx.x * 16) >> 12;
        atomicAdd(&g_pool_sum[bb*PLV + t], bsum[t]);
        atomicMax(&g_pool_max[bb*PLV + t], bmx[t]);
    }
}

// ---------------- GENERAL EM (flag-gated fallback) ----------------
__global__ __launch_bounds__(256, 1)
void em_general(const float* __restrict__ binit)
{
    __shared__ int sflag;
    if (threadIdx.x == 0) sflag = g_nonuni;
    __syncthreads();
    if (!sflag) return;

    __shared__ float bsum[PLV];
    __shared__ int   bmx[PLV];
    const int t = threadIdx.x;
    bsum[t] = 0.f; bmx[t] = 0;
    __syncthreads();

    const int w = t >> 5, lane = t & 31;
    const int m = blockIdx.x * 8 + w;

    float b[RRV];
#pragma unroll
    for (int r = 0; r < RRV; r++) {
        const float v = binit[m*RRV + r];
        b[r] = v / fmaxf(fabsf(v), 1e-12f);
    }
    bool uni = true;
#pragma unroll
    for (int r = 1; r < RRV; r++) uni &= (b[r] == b[0]);

    bool did = false;
    if (!uni) {
        did = true;
        float x[8];
#pragma unroll
        for (int j = 0; j < 8; j++) x[j] = g_xl[(size_t)m*PLV + lane + 32*j];

        float cf[8][RRV];
#pragma unroll
        for (int j = 0; j < 8; j++) {
            const float xn = x[j];
            float tv[RRV]; float mx = -3.4e38f;
#pragma unroll
            for (int r = 0; r < RRV; r++) { tv[r] = xn * b[r]; mx = fmaxf(mx, tv[r]); }
            float s = 0.f;
#pragma unroll
            for (int r = 0; r < RRV; r++) { const float e = __expf(tv[r]-mx); cf[j][r]=e; s+=e; }
            const float inv = __fdividef(1.f, s);
#pragma unroll
            for (int r = 0; r < RRV; r++) cf[j][r] *= inv;
        }
        for (int step = 0; step < STEPSV; step++) {
#pragma unroll
            for (int j = 0; j < 8; j++) {
                float s = 0.f;
#pragma unroll
                for (int r = 0; r < RRV; r++) s = fmaf(cf[j][r], b[r], s);
                const float xn = x[j];
#pragma unroll
                for (int r = 0; r < RRV; r++) {
                    const float num = xn * b[r];
                    const float den = fmaf(s, b[r], EPSV);
                    cf[j][r] = cf[j][r] * num * __fdividef(1.f, den);
                }
            }
            float p[RRV], q[RRV];
#pragma unroll
            for (int r = 0; r < RRV; r++) { p[r]=0.f; q[r]=0.f; }
#pragma unroll
            for (int j = 0; j < 8; j++) {
                float sp = 0.f;
#pragma unroll
                for (int r = 0; r < RRV; r++) sp = fmaf(cf[j][r], b[r], sp);
                const float xn = x[j];
#pragma unroll
                for (int r = 0; r < RRV; r++) {
                    p[r] = fmaf(xn, cf[j][r], p[r]);
                    q[r] = fmaf(sp, cf[j][r], q[r]);
                }
            }
#pragma unroll
            for (int off = 16; off > 0; off >>= 1) {
#pragma unroll
                for (int r = 0; r < RRV; r++) {
                    p[r] += __shfl_xor_sync(0xffffffffu, p[r], off);
                    q[r] += __shfl_xor_sync(0xffffffffu, q[r], off);
                }
            }
#pragma unroll
            for (int r = 0; r < RRV; r++)
                b[r] = b[r] * p[r] * __fdividef(1.f, q[r] + EPSV);
        }
#pragma unroll
        for (int j = 0; j < 8; j++) {
            float s = 0.f;
#pragma unroll
            for (int r = 0; r < RRV; r++) s = fmaf(cf[j][r], b[r], s);
            const float xn = x[j];
#pragma unroll
            for (int r = 0; r < RRV; r++) {
                const float num = xn * b[r];
                const float den = fmaf(s, b[r], EPSV);
                cf[j][r] = cf[j][r] * num * __fdividef(1.f, den);
            }
        }
#pragma unroll
        for (int j = 0; j < 8; j++) {
            float xr = 0.f;
#pragma unroll
            for (int r = 0; r < RRV; r++) xr = fmaf(b[r], cf[j][r], xr);
            const int n = lane + 32*j;
            const float f = fmaxf(g_xm[(size_t)m*PLV + n] + xr, 0.f);
            const __nv_bfloat16 hi = __float2bfloat16(f);
            g_feath[(size_t)m*PLV + n] = hi;
            g_featl[(size_t)m*PLV + n] = __float2bfloat16(f - __bfloat162float(hi));
            atomicAdd(&bsum[n], f);
            atomicMax(&bmx[n], __float_as_int(f));
        }
    }
    __syncthreads();
    if (__syncthreads_or(did)) {
        const int bb = (blockIdx.x * 8) >> 12;
        atomicAdd(&g_pool_sum[bb*PLV + t], bsum[t]);
        atomicMax(&g_pool_max[bb*PLV + t], bmx[t]);
    }
}

// ---------------- channel attention ----------------
__global__ __launch_bounds__(256)
void ca_kernel(const float* __restrict__ ca1, const float* __restrict__ ca2,
               float* __restrict__ out)
{
    const int b = blockIdx.x;
    const int t = threadIdx.x;
    __shared__ float sAvg[PLV], sMx[PLV], h1[ATTV];
    sAvg[t] = g_pool_sum[b*PLV + t] * (1.0f/(float)HWV);
    sMx[t]  = __int_as_float(g_pool_max[b*PLV + t]);
    __syncthreads();
    if (t < ATTV) {
        float a1 = 0.f, a2 = 0.f;
        for (int p = 0; p < PLV; p++) {
            const float wv = ca1[t*PLV + p];
            a1 = fmaf(wv, sAvg[p], a1);
            a2 = fmaf(wv, sMx[p],  a2);
        }
        h1[t] = fmaxf(a1, 0.f) + fmaxf(a2, 0.f);
    }
    __syncthreads();
    float v = 0.f;
    for (int a = 0; a < ATTV; a++) v = fmaf(h1[a], ca2[t*ATTV + a], v);
    const float att = __fdividef(1.f, 1.f + __expf(-v));
    g_att[b*PLV + t] = att;
    out[(size_t)BTOT*CINV*HWV + b*PLV + t] = att;
}

// ---------------- fc B pre-scale + split: fw[n][k]*att[b][k] ----------------
__global__ void fcb_kernel(const float* __restrict__ fw)
{
    const int idx = blockIdx.x * 256 + threadIdx.x;   // grid 128 -> 32768 over [128][256]
    const int n = idx >> 8, k = idx & 255;
    const float w = fw[n*PLV + k];
#pragma unroll
    for (int b = 0; b < BTOT; b++) {
        const float v = w * g_att[b*PLV + k];
        const __nv_bfloat16 hi = __float2bfloat16(v);
        const size_t o = (size_t)(b*CINV + n)*PLV + k;
        g_fwbh[o] = hi;
        g_fwbl[o] = __float2bfloat16(v - __bfloat162float(hi));
    }
}

// ---------------- launch ----------------
extern "C" void kernel_launch(void* const* d_in, const int* in_sizes, int n_in,
                              void* d_out, int out_size)
{
    const float* x       = (const float*)d_in[0];
    const float* conv1_w = (const float*)d_in[1];
    const float* conv3_w = (const float*)d_in[2];
    const float* conv3_b = (const float*)d_in[3];
    const float* lower_w = (const float*)d_in[4];
    const float* lower_b = (const float*)d_in[5];
    const float* ca1_w   = (const float*)d_in[6];
    const float* ca2_w   = (const float*)d_in[7];
    const float* fc_w    = (const float*)d_in[8];
    const float* fc_b    = (const float*)d_in[9];
    const float* bases   = (const float*)d_in[10];
    float* out = (float*)d_out;

    static int smem_set = 0;
    if (!smem_set) {
        cudaFuncSetAttribute(conv1_mma_kernel,
                             cudaFuncAttributeMaxDynamicSharedMemorySize, LM_SMEM);
        cudaFuncSetAttribute(mma_pipe_kernel<1>,
                             cudaFuncAttributeMaxDynamicSharedMemorySize, PIPE_SMEM);
        cudaFuncSetAttribute(mma_pipe_kernel<2>,
                             cudaFuncAttributeMaxDynamicSharedMemorySize, PIPE_SMEM);
        smem_set = 1;
    }

    // device-global pointers usable from host via symbols not needed: pass via kernel args
    __nv_bfloat16 *xmh, *xml, *lwh, *lwl, *fth, *ftl, *fwh, *fwl;
    cudaGetSymbolAddress((void**)&xmh, g_xmh);
    cudaGetSymbolAddress((void**)&xml, g_xml);
    cudaGetSymbolAddress((void**)&lwh, g_lwh);
    cudaGetSymbolAddress((void**)&lwl, g_lwl);
    cudaGetSymbolAddress((void**)&fth, g_feath);
    cudaGetSymbolAddress((void**)&ftl, g_featl);
    cudaGetSymbolAddress((void**)&fwh, g_fwbh);
    cudaGetSymbolAddress((void**)&fwl, g_fwbl);

    init_kernel<<<256, 256>>>(lower_w);
    conv1_mma_kernel<<<dim3(MTOT/128, PLV/128), 256, LM_SMEM>>>(x, conv1_w);
    dw_kernel<<<MTOT/16, 256>>>(conv3_w, conv3_b);
    mma_pipe_kernel<1><<<dim3(MTOT/128, PLV/128), 256, PIPE_SMEM>>>(
        xmh, xml, lwh, lwl, lower_b, nullptr);
    em_fast<<<MTOT/16, 512>>>(bases);
    em_general<<<MTOT/8, 256>>>(bases);
    ca_kernel<<<BTOT, 256>>>(ca1_w, ca2_w, out);
    fcb_kernel<<<128, 256>>>(fc_w);
    mma_pipe_kernel<2><<<dim3(MTOT/128, 1), 256, PIPE_SMEM>>>(
        fth, ftl, fwh, fwl, fc_b, out);
}

// round 11
// speedup vs baseline: 1.6760x; 1.0048x over previous
#include <cuda_runtime.h>
#include <cuda_bf16.h>
#include <math.h>
#include <stdint.h>

#define BTOT 4
#define CINV 128
#define HHV 64
#define WWV 64
#define PLV 256
#define ATTV 64
#define RRV 16
#define STEPSV 6
#define EPSV 1e-6f
#define MTOT (BTOT*HHV*WWV)   /* 16384 */
#define HWV (HHV*WWV)         /* 4096 */

// ---------------- scratch (device globals; no runtime allocation) ----------------
__device__ float g_y[MTOT*PLV];        // conv1 output, NHWC
__device__ float g_xm[MTOT*PLV];       // depthwise+bias output, NHWC fp32
__device__ float g_xl[MTOT*PLV];       // relu(lower) output
__device__ __nv_bfloat16 g_xmh[MTOT*PLV], g_xml[MTOT*PLV];     // xm split
__device__ __nv_bfloat16 g_feath[MTOT*PLV], g_featl[MTOT*PLV]; // feat split
__device__ __nv_bfloat16 g_lwh[PLV*PLV], g_lwl[PLV*PLV];       // lower_w split
__device__ __nv_bfloat16 g_fwbh[BTOT*CINV*PLV], g_fwbl[BTOT*CINV*PLV]; // fc_w*att split
__device__ float g_att[BTOT*PLV];
__device__ float g_pool_sum[BTOT*PLV];
__device__ int   g_pool_max[BTOT*PLV];
__device__ int   g_nonuni;

// ---------------- MMA/ldmatrix helpers (mappings validated rounds 7-8) ------------
__device__ __forceinline__ uint32_t smem_u32(const void* p) {
    uint32_t a;
    asm("{ .reg .u64 tmp; cvta.to.shared.u64 tmp, %1; cvt.u32.u64 %0, tmp; }"
        : "=r"(a) : "l"(p));
    return a;
}
__device__ __forceinline__ void ldm_x4(uint32_t* r, uint32_t addr) {
    asm volatile("ldmatrix.sync.aligned.m8n8.x4.shared.b16 {%0,%1,%2,%3}, [%4];"
        : "=r"(r[0]), "=r"(r[1]), "=r"(r[2]), "=r"(r[3]) : "r"(addr));
}
__device__ __forceinline__ void ldm_x4_t(uint32_t* r, uint32_t addr) {
    asm volatile("ldmatrix.sync.aligned.m8n8.x4.trans.shared.b16 {%0,%1,%2,%3}, [%4];"
        : "=r"(r[0]), "=r"(r[1]), "=r"(r[2]), "=r"(r[3]) : "r"(addr));
}
__device__ __forceinline__ void mma_bf16(float* c, const uint32_t* a, const uint32_t* b) {
    asm volatile("mma.sync.aligned.m16n8k16.row.col.f32.bf16.bf16.f32 "
        "{%0,%1,%2,%3},{%4,%5,%6,%7},{%8,%9},{%0,%1,%2,%3};"
        : "+f"(c[0]), "+f"(c[1]), "+f"(c[2]), "+f"(c[3])
        : "r"(a[0]), "r"(a[1]), "r"(a[2]), "r"(a[3]), "r"(b[0]), "r"(b[1]));
}
__device__ __forceinline__ uint32_t pack_hi(float x, float y) {
    __nv_bfloat162 h; h.x = __float2bfloat16(x); h.y = __float2bfloat16(y);
    return *(uint32_t*)&h;
}
__device__ __forceinline__ uint32_t pack_lo(float x, float y) {
    __nv_bfloat162 h;
    h.x = __float2bfloat16(x - __bfloat162float(__float2bfloat16(x)));
    h.y = __float2bfloat16(y - __bfloat162float(__float2bfloat16(y)));
    return *(uint32_t*)&h;
}
#define CP16(d, s) \
    asm volatile("cp.async.ca.shared.global [%0], [%1], 16;" :: "r"(d), "l"(s))

#define LM_ROWE 72
#define LM_OFSB (128*LM_ROWE*2)            /* 18432 B per [128][72] bf16 buffer */
#define PIPE_STAGE (4*LM_OFSB)             /* 73728 B */
#define PIPE_SMEM  (2*PIPE_STAGE)          /* 147456 B */
#define LM_SMEM (4*LM_OFSB)                /* conv1 (single-stage) */

#define C1_AROW 272
#define C1_AOFS (64*C1_AROW)

// ---------------- init: zero pools/flag + split lower_w ----------------
__global__ void init_kernel(const float* __restrict__ lw)
{
    int i = blockIdx.x * 256 + threadIdx.x;     // grid 256 -> 65536
    if (i == 0) g_nonuni = 0;
    if (i < BTOT*PLV) { g_pool_sum[i] = 0.f; g_pool_max[i] = 0; }
    if (i < PLV*PLV) {
        const float v = lw[i];
        const __nv_bfloat16 h = __float2bfloat16(v);
        g_lwh[i] = h;
        g_lwl[i] = __float2bfloat16(v - __bfloat162float(h));
    }
}

// ------------- conv1 MMA (round-8 proven, unchanged) ------------------------------
__global__ __launch_bounds__(256)
void conv1_mma_kernel(const float* __restrict__ x, const float* __restrict__ w1)
{
    extern __shared__ char sm[];
    const uint32_t sbase = smem_u32(sm);
    char* pAH = sm;
    char* pAL = sm + C1_AOFS;
    char* pBH = sm + 2*C1_AOFS;
    char* pBL = sm + 2*C1_AOFS + LM_OFSB;
    const uint32_t oAH = 0, oAL = C1_AOFS, oBH = 2*C1_AOFS, oBL = 2*C1_AOFS + LM_OFSB;

    const int t = threadIdx.x, lane = t & 31, wid = t >> 5;
    const int m0 = blockIdx.x * 128;
    const int n0 = blockIdx.y * 128;
    const int batch = m0 >> 12;
    const int pix0 = m0 & (HWV - 1);
    const int wm = (wid & 3) * 32;
    const int wn = (wid >> 2) * 64;

    float acc[2][8][4];
#pragma unroll
    for (int a = 0; a < 2; a++)
#pragma unroll
        for (int b = 0; b < 8; b++)
#pragma unroll
            for (int q = 0; q < 4; q++) acc[a][b][q] = 0.f;

#pragma unroll 1
    for (int c = 0; c < 2; c++) {
        const int k0 = c * 64;
#pragma unroll
        for (int i = 0; i < 8; i++) {
            const int idx = t + 256*i;
            const int row = idx >> 5;
            const int mc  = (idx & 31) << 2;
            const float4 v = *(const float4*)(x + (size_t)batch*CINV*HWV
                                              + (size_t)(k0+row)*HWV + pix0 + mc);
            const uint32_t off = (uint32_t)(row*C1_AROW + mc*2);
            *(uint2*)(pAH + off) = make_uint2(pack_hi(v.x,v.y), pack_hi(v.z,v.w));
            *(uint2*)(pAL + off) = make_uint2(pack_lo(v.x,v.y), pack_lo(v.z,v.w));
        }
#pragma unroll
        for (int i = 0; i < 8; i++) {
            const int idx = t + 256*i;
            const int row = idx >> 4;
            const int c4  = (idx & 15) << 2;
            const float4 v = *(const float4*)(w1 + (size_t)(n0+row)*CINV + k0 + c4);
            const uint32_t off = (uint32_t)(row*(LM_ROWE*2) + c4*2);
            *(uint2*)(pBH + off) = make_uint2(pack_hi(v.x,v.y), pack_hi(v.z,v.w));
            *(uint2*)(pBL + off) = make_uint2(pack_lo(v.x,v.y), pack_lo(v.z,v.w));
        }
        __syncthreads();

#pragma unroll
        for (int ks = 0; ks < 4; ks++) {
            uint32_t ah[2][4], al[2][4];
            const int q = lane >> 3;
            const uint32_t krow = ks*16 + ((q & 2) << 2) + (lane & 7);
#pragma unroll
            for (int mf = 0; mf < 2; mf++) {
                const uint32_t mc = wm + mf*16 + ((q & 1) << 3);
                const uint32_t o  = krow*C1_AROW + mc*2;
                ldm_x4_t(ah[mf], sbase + oAH + o);
                ldm_x4_t(al[mf], sbase + oAL + o);
            }
#pragma unroll
            for (int g = 0; g < 4; g++) {
                uint32_t bh[4], bl[4];
                const uint32_t nrow = wn + g*16 + (lane & 7) + (((lane >> 4) & 1) << 3);
                const uint32_t kcol = ks*16 + (((lane >> 3) & 1) << 3);
                const uint32_t o    = nrow*(LM_ROWE*2) + kcol*2;
                ldm_x4(bh, sbase + oBH + o);
                ldm_x4(bl, sbase + oBL + o);
#pragma unroll
                for (int h = 0; h < 2; h++) {
                    const int nf = g*2 + h;
#pragma unroll
                    for (int mf = 0; mf < 2; mf++) {
                        mma_bf16(acc[mf][nf], ah[mf], &bh[h*2]);
                        mma_bf16(acc[mf][nf], ah[mf], &bl[h*2]);
                        mma_bf16(acc[mf][nf], al[mf], &bh[h*2]);
                    }
                }
            }
        }
        __syncthreads();
    }

#pragma unroll
    for (int mf = 0; mf < 2; mf++) {
        const int r0 = m0 + wm + mf*16 + (lane >> 2);
#pragma unroll
        for (int nf = 0; nf < 8; nf++) {
            const int col = n0 + wn + nf*8 + ((lane & 3) << 1);
            float2 v0, v1;
            v0.x = acc[mf][nf][0]; v0.y = acc[mf][nf][1];
            v1.x = acc[mf][nf][2]; v1.y = acc[mf][nf][3];
            *(float2*)&g_y[(size_t)r0*PLV + col]     = v0;
            *(float2*)&g_y[(size_t)(r0+8)*PLV + col] = v1;
        }
    }
}

// ------------- pipelined MMA (cp.async double-buffered, pre-split bf16) -----------
// MODE 1: xl = relu(A@B^T + bias)   A=g_xmh/l rows m0, B=g_lwh/l rows n0
// MODE 2: out = A@B^T + bias, NCHW  A=g_feath/l rows m0, B=g_fwbh/l rows batch*128
template<int MODE>
__global__ __launch_bounds__(256)
void mma_pipe_kernel(const __nv_bfloat16* __restrict__ Ah, const __nv_bfloat16* __restrict__ Al,
                     const __nv_bfloat16* __restrict__ Bh, const __nv_bfloat16* __restrict__ Bl,
                     const float* __restrict__ bias, float* __restrict__ outp)
{
    extern __shared__ char sm[];
    const uint32_t sbase = smem_u32(sm);

    const int t = threadIdx.x, lane = t & 31, wid = t >> 5;
    const int m0 = blockIdx.x * 128;
    const int n0 = (MODE == 1) ? blockIdx.y * 128 : 0;
    const int batch = m0 >> 12;
    const int brow0 = (MODE == 1) ? n0 : batch * 128;
    const int wm = (wid & 3) * 32;
    const int wn = (wid >> 2) * 64;

#define PREFETCH(STG, CC) do {                                                   \
        const int _k0 = (CC) * 64;                                               \
        _Pragma("unroll")                                                        \
        for (int _a = 0; _a < 4; _a++) {                                         \
            const __nv_bfloat16* _src = (_a==0)?Ah:(_a==1)?Al:(_a==2)?Bh:Bl;     \
            const int _rb = (_a < 2) ? m0 : brow0;                               \
            _Pragma("unroll")                                                    \
            for (int _ii = 0; _ii < 4; _ii++) {                                  \
                const int _j = t + 256*_ii;                                      \
                const int _row = _j >> 3, _seg = _j & 7;                         \
                const uint32_t _d = sbase + (STG)*PIPE_STAGE + _a*LM_OFSB        \
                                    + _row*(LM_ROWE*2) + _seg*16;                \
                CP16(_d, _src + (size_t)(_rb+_row)*PLV + _k0 + _seg*8);          \
            }                                                                    \
        }                                                                        \
        asm volatile("cp.async.commit_group;");                                  \
    } while (0)

    float acc[2][8][4];
#pragma unroll
    for (int a = 0; a < 2; a++)
#pragma unroll
        for (int b = 0; b < 8; b++)
#pragma unroll
            for (int q = 0; q < 4; q++) acc[a][b][q] = 0.f;

    PREFETCH(0, 0);

#pragma unroll 1
    for (int c = 0; c < 4; c++) {
        if (c < 3) {
            PREFETCH((c + 1) & 1, c + 1);
            asm volatile("cp.async.wait_group 1;");
        } else {
            asm volatile("cp.async.wait_group 0;");
        }
        __syncthreads();
        const uint32_t sb = sbase + (c & 1) * PIPE_STAGE;

#pragma unroll
        for (int ks = 0; ks < 4; ks++) {
            uint32_t ah[2][4], al[2][4];
#pragma unroll
            for (int mf = 0; mf < 2; mf++) {
                const uint32_t r   = wm + mf*16 + (lane & 15);
                const uint32_t col = ks*16 + ((lane >> 4) << 3);
                const uint32_t o   = r * (LM_ROWE*2) + col * 2;
                ldm_x4(ah[mf], sb + 0*LM_OFSB + o);
                ldm_x4(al[mf], sb + 1*LM_OFSB + o);
            }
#pragma unroll
            for (int g = 0; g < 4; g++) {
                uint32_t bh[4], bl[4];
                const uint32_t nrow = wn + g*16 + (lane & 7) + (((lane >> 4) & 1) << 3);
                const uint32_t kcol = ks*16 + (((lane >> 3) & 1) << 3);
                const uint32_t o    = nrow * (LM_ROWE*2) + kcol * 2;
                ldm_x4(bh, sb + 2*LM_OFSB + o);
                ldm_x4(bl, sb + 3*LM_OFSB + o);
#pragma unroll
                for (int h = 0; h < 2; h++) {
                    const int nf = g*2 + h;
#pragma unroll
                    for (int mf = 0; mf < 2; mf++) {
                        mma_bf16(acc[mf][nf], ah[mf], &bh[h*2]);
                        mma_bf16(acc[mf][nf], ah[mf], &bl[h*2]);
                        mma_bf16(acc[mf][nf], al[mf], &bh[h*2]);
                    }
                }
            }
        }
        __syncthreads();
    }
#undef PREFETCH

    if (MODE == 1) {
#pragma unroll
        for (int mf = 0; mf < 2; mf++) {
            const int r0 = m0 + wm + mf*16 + (lane >> 2);
#pragma unroll
            for (int nf = 0; nf < 8; nf++) {
                const int col = n0 + wn + nf*8 + ((lane & 3) << 1);
                const float b0v = bias[col], b1v = bias[col+1];
                float2 v0, v1;
                v0.x = fmaxf(acc[mf][nf][0] + b0v, 0.f);
                v0.y = fmaxf(acc[mf][nf][1] + b1v, 0.f);
                v1.x = fmaxf(acc[mf][nf][2] + b0v, 0.f);
                v1.y = fmaxf(acc[mf][nf][3] + b1v, 0.f);
                *(float2*)&g_xl[(size_t)r0*PLV + col]     = v0;
                *(float2*)&g_xl[(size_t)(r0+8)*PLV + col] = v1;
            }
        }
    } else {
        // NCHW epilogue via smem staging: st[pix 128][ch 128] stride 130
        float* st = (float*)sm;
        const int pixbase = m0 & (HWV - 1);
#pragma unroll
        for (int mf = 0; mf < 2; mf++) {
            const int r0 = wm + mf*16 + (lane >> 2);
#pragma unroll
            for (int nf = 0; nf < 8; nf++) {
                const int col = wn + nf*8 + ((lane & 3) << 1);
                const float b0v = bias[col], b1v = bias[col+1];
                st[r0*130 + col]         = acc[mf][nf][0] + b0v;
                st[r0*130 + col + 1]     = acc[mf][nf][1] + b1v;
                st[(r0+8)*130 + col]     = acc[mf][nf][2] + b0v;
                st[(r0+8)*130 + col + 1] = acc[mf][nf][3] + b1v;
            }
        }
        __syncthreads();
        const int chb = t >> 5;
#pragma unroll
        for (int cp = 0; cp < 16; cp++) {
            const int ch = chb + 8*cp;
#pragma unroll
            for (int pbk = 0; pbk < 4; pbk++) {
                const int pix = pbk*32 + lane;
                outp[(size_t)(batch*CINV + ch)*HWV + pixbase + pix] = st[pix*130 + ch];
            }
        }
    }
}

// ------------- depthwise 3x3 + bias, NHWC; writes fp32 + split bf16 ---------------
__global__ __launch_bounds__(256)
void dw_kernel(const float* __restrict__ w3, const float* __restrict__ b3)
{
    const int p = threadIdx.x;
    float wv[9];
#pragma unroll
    for (int j = 0; j < 9; j++) wv[j] = w3[p*9 + j];
    const float bb = b3[p];

    const int pix0 = blockIdx.x * 16;
    const int b = pix0 >> 12, hw = pix0 & 4095, h = hw >> 6, w0 = hw & 63;
    const size_t rowm = (h > 0)      ? ((size_t)((b<<12) + ((h-1)<<6)) * PLV + p) : 0;
    const size_t rowc = (size_t)((b<<12) + (h<<6)) * PLV + p;
    const size_t rowp = (h < HHV-1)  ? ((size_t)((b<<12) + ((h+1)<<6)) * PLV + p) : 0;
    const bool hm = (h > 0), hp = (h < HHV-1);

    float a0,a1,a2, c0,c1,c2;
    if (w0 > 0) {
        a0 = hm ? g_y[rowm + (size_t)(w0-1)*PLV] : 0.f;
        a1 =      g_y[rowc + (size_t)(w0-1)*PLV];
        a2 = hp ? g_y[rowp + (size_t)(w0-1)*PLV] : 0.f;
    } else { a0 = a1 = a2 = 0.f; }
    c0 = hm ? g_y[rowm + (size_t)w0*PLV] : 0.f;
    c1 =      g_y[rowc + (size_t)w0*PLV];
    c2 = hp ? g_y[rowp + (size_t)w0*PLV] : 0.f;

#pragma unroll
    for (int k = 0; k < 16; k++) {
        const int ww = w0 + k + 1;
        float n0v, n1v, n2v;
        if (ww < WWV) {
            n0v = hm ? g_y[rowm + (size_t)ww*PLV] : 0.f;
            n1v =      g_y[rowc + (size_t)ww*PLV];
            n2v = hp ? g_y[rowp + (size_t)ww*PLV] : 0.f;
        } else { n0v = n1v = n2v = 0.f; }

        float acc = bb;
        acc = fmaf(a0, wv[0], acc); acc = fmaf(c0, wv[1], acc); acc = fmaf(n0v, wv[2], acc);
        acc = fmaf(a1, wv[3], acc); acc = fmaf(c1, wv[4], acc); acc = fmaf(n1v, wv[5], acc);
        acc = fmaf(a2, wv[6], acc); acc = fmaf(c2, wv[7], acc); acc = fmaf(n2v, wv[8], acc);
        const size_t o = (size_t)(pix0 + k)*PLV + p;
        g_xm[o] = acc;
        const __nv_bfloat16 hi = __float2bfloat16(acc);
        g_xmh[o] = hi;
        g_xml[o] = __float2bfloat16(acc - __bfloat162float(hi));

        a0 = c0; a1 = c1; a2 = c2;
        c0 = n0v; c1 = n1v; c2 = n2v;
    }
}

// ---------------- FAST EM (writes feat as split bf16) ----------------
__global__ __launch_bounds__(512)
void em_fast(const float* __restrict__ binit)
{
    __shared__ float bsum[PLV];
    __shared__ int   bmx[PLV];
    const int t = threadIdx.x;
    if (t < PLV) { bsum[t] = 0.f; bmx[t] = 0; }
    __syncthreads();

    const int w = t >> 5, lane = t & 31;
    const int m = blockIdx.x * 16 + w;

    float bv = 1.f;
    if (lane < RRV) {
        const float v = binit[m*RRV + lane];
        bv = v / fmaxf(fabsf(v), 1e-12f);
    }
    const float b0 = __shfl_sync(0xffffffffu, bv, 0);
    const bool uni = __all_sync(0xffffffffu, (lane >= RRV) || (bv == b0));

    if (uni) {
        float b = b0;
        float x[8], cf[8];
        {
            const float4 v0 = *(const float4*)(g_xl + (size_t)m*PLV + lane*8);
            const float4 v1 = *(const float4*)(g_xl + (size_t)m*PLV + lane*8 + 4);
            x[0]=v0.x; x[1]=v0.y; x[2]=v0.z; x[3]=v0.w;
            x[4]=v1.x; x[5]=v1.y; x[6]=v1.z; x[7]=v1.w;
        }
#pragma unroll
        for (int j = 0; j < 8; j++) cf[j] = 0.0625f;

#pragma unroll
        for (int step = 0; step < STEPSV; step++) {
            float ps = 0.f, qs = 0.f;
#pragma unroll
            for (int j = 0; j < 8; j++) {
                const float tb  = cf[j] * b;
                const float den = fmaf(16.f*tb, b, EPSV);
                const float num = x[j] * b;
                cf[j] = cf[j] * num * __fdividef(1.f, den);
                ps = fmaf(x[j],  cf[j], ps);
                qs = fmaf(cf[j], cf[j], qs);
            }
#pragma unroll
            for (int off = 16; off > 0; off >>= 1) {
                ps += __shfl_xor_sync(0xffffffffu, ps, off);
                qs += __shfl_xor_sync(0xffffffffu, qs, off);
            }
            const float den = fmaf(16.f*b, qs, EPSV);
            b = b * ps * __fdividef(1.f, den);
        }
#pragma unroll
        for (int j = 0; j < 8; j++) {
            const float tb  = cf[j] * b;
            const float den = fmaf(16.f*tb, b, EPSV);
            const float num = x[j] * b;
            cf[j] = cf[j] * num * __fdividef(1.f, den);
        }
        const float4 m0v = *(const float4*)(g_xm + (size_t)m*PLV + lane*8);
        const float4 m1v = *(const float4*)(g_xm + (size_t)m*PLV + lane*8 + 4);
        const float xm8[8] = {m0v.x,m0v.y,m0v.z,m0v.w,m1v.x,m1v.y,m1v.z,m1v.w};
        float f[8];
#pragma unroll
        for (int j = 0; j < 8; j++) {
            f[j] = fmaxf(fmaf(16.f*b, cf[j], xm8[j]), 0.f);
            const int n = lane*8 + j;
            atomicAdd(&bsum[n], f[j]);
            atomicMax(&bmx[n], __float_as_int(f[j]));
        }
        uint4 hi, lo;
        hi.x = pack_hi(f[0],f[1]); hi.y = pack_hi(f[2],f[3]);
        hi.z = pack_hi(f[4],f[5]); hi.w = pack_hi(f[6],f[7]);
        lo.x = pack_lo(f[0],f[1]); lo.y = pack_lo(f[2],f[3]);
        lo.z = pack_lo(f[4],f[5]); lo.w = pack_lo(f[6],f[7]);
        *(uint4*)&g_feath[(size_t)m*PLV + lane*8] = hi;
        *(uint4*)&g_featl[(size_t)m*PLV + lane*8] = lo;
    } else if (lane == 0) {
        g_nonuni = 1;
    }
    __syncthreads();
    if (t < PLV) {
        const int bb = (blockIdx.x * 16) >> 12;
        atomicAdd(&g_pool_sum[bb*PLV + t], bsum[t]);
        atomicMax(&g_pool_max[bb*PLV + t], bmx[t]);
    }
}

// ---------------- GENERAL EM (flag-gated fallback) ----------------
__global__ __launch_bounds__(256, 1)
void em_general(const float* __restrict__ binit)
{
    __shared__ int sflag;
    if (threadIdx.x == 0) sflag = g_nonuni;
    __syncthreads();
    if (!sflag) return;

    __shared__ float bsum[PLV];
    __shared__ int   bmx[PLV];
    const int t = threadIdx.x;
    bsum[t] = 0.f; bmx[t] = 0;
    __syncthreads();

    const int w = t >> 5, lane = t & 31;
    const int m = blockIdx.x * 8 + w;

    float b[RRV];
#pragma unroll
    for (int r = 0; r < RRV; r++) {
        const float v = binit[m*RRV + r];
        b[r] = v / fmaxf(fabsf(v), 1e-12f);
    }
    bool uni = true;
#pragma unroll
    for (int r = 1; r < RRV; r++) uni &= (b[r] == b[0]);

    bool did = false;
    if (!uni) {
        did = true;
        float x[8];
#pragma unroll
        for (int j = 0; j < 8; j++) x[j] = g_xl[(size_t)m*PLV + lane + 32*j];

        float cf[8][RRV];
#pragma unroll
        for (int j = 0; j < 8; j++) {
            const float xn = x[j];
            float tv[RRV]; float mx = -3.4e38f;
#pragma unroll
            for (int r = 0; r < RRV; r++) { tv[r] = xn * b[r]; mx = fmaxf(mx, tv[r]); }
            float s = 0.f;
#pragma unroll
            for (int r = 0; r < RRV; r++) { const float e = __expf(tv[r]-mx); cf[j][r]=e; s+=e; }
            const float inv = __fdividef(1.f, s);
#pragma unroll
            for (int r = 0; r < RRV; r++) cf[j][r] *= inv;
        }
        for (int step = 0; step < STEPSV; step++) {
#pragma unroll
            for (int j = 0; j < 8; j++) {
                float s = 0.f;
#pragma unroll
                for (int r = 0; r < RRV; r++) s = fmaf(cf[j][r], b[r], s);
                const float xn = x[j];
#pragma unroll
                for (int r = 0; r < RRV; r++) {
                    const float num = xn * b[r];
                    const float den = fmaf(s, b[r], EPSV);
                    cf[j][r] = cf[j][r] * num * __fdividef(1.f, den);
                }
            }
            float p[RRV], q[RRV];
#pragma unroll
            for (int r = 0; r < RRV; r++) { p[r]=0.f; q[r]=0.f; }
#pragma unroll
            for (int j = 0; j < 8; j++) {
                float sp = 0.f;
#pragma unroll
                for (int r = 0; r < RRV; r++) sp = fmaf(cf[j][r], b[r], sp);
                const float xn = x[j];
#pragma unroll
                for (int r = 0; r < RRV; r++) {
                    p[r] = fmaf(xn, cf[j][r], p[r]);
                    q[r] = fmaf(sp, cf[j][r], q[r]);
                }
            }
#pragma unroll
            for (int off = 16; off > 0; off >>= 1) {
#pragma unroll
                for (int r = 0; r < RRV; r++) {
                    p[r] += __shfl_xor_sync(0xffffffffu, p[r], off);
                    q[r] += __shfl_xor_sync(0xffffffffu, q[r], off);
                }
            }
#pragma unroll
            for (int r = 0; r < RRV; r++)
                b[r] = b[r] * p[r] * __fdividef(1.f, q[r] + EPSV);
        }
#pragma unroll
        for (int j = 0; j < 8; j++) {
            float s = 0.f;
#pragma unroll
            for (int r = 0; r < RRV; r++) s = fmaf(cf[j][r], b[r], s);
            const float xn = x[j];
#pragma unroll
            for (int r = 0; r < RRV; r++) {
                const float num = xn * b[r];
                const float den = fmaf(s, b[r], EPSV);
                cf[j][r] = cf[j][r] * num * __fdividef(1.f, den);
            }
        }
#pragma unroll
        for (int j = 0; j < 8; j++) {
            float xr = 0.f;
#pragma unroll
            for (int r = 0; r < RRV; r++) xr = fmaf(b[r], cf[j][r], xr);
            const int n = lane + 32*j;
            const float f = fmaxf(g_xm[(size_t)m*PLV + n] + xr, 0.f);
            const __nv_bfloat16 hi = __float2bfloat16(f);
            g_feath[(size_t)m*PLV + n] = hi;
            g_featl[(size_t)m*PLV + n] = __float2bfloat16(f - __bfloat162float(hi));
            atomicAdd(&bsum[n], f);
            atomicMax(&bmx[n], __float_as_int(f));
        }
    }
    __syncthreads();
    if (__syncthreads_or(did)) {
        const int bb = (blockIdx.x * 8) >> 12;
        atomicAdd(&g_pool_sum[bb*PLV + t], bsum[t]);
        atomicMax(&g_pool_max[bb*PLV + t], bmx[t]);
    }
}

// ---------------- channel attention ----------------
__global__ __launch_bounds__(256)
void ca_kernel(const float* __restrict__ ca1, const float* __restrict__ ca2,
               float* __restrict__ out)
{
    const int b = blockIdx.x;
    const int t = threadIdx.x;
    __shared__ float sAvg[PLV], sMx[PLV], h1[ATTV];
    sAvg[t] = g_pool_sum[b*PLV + t] * (1.0f/(float)HWV);
    sMx[t]  = __int_as_float(g_pool_max[b*PLV + t]);
    __syncthreads();
    if (t < ATTV) {
        float a1 = 0.f, a2 = 0.f;
        for (int p = 0; p < PLV; p++) {
            const float wv = ca1[t*PLV + p];
            a1 = fmaf(wv, sAvg[p], a1);
            a2 = fmaf(wv, sMx[p],  a2);
        }
        h1[t] = fmaxf(a1, 0.f) + fmaxf(a2, 0.f);
    }
    __syncthreads();
    float v = 0.f;
    for (int a = 0; a < ATTV; a++) v = fmaf(h1[a], ca2[t*ATTV + a], v);
    const float att = __fdividef(1.f, 1.f + __expf(-v));
    g_att[b*PLV + t] = att;
    out[(size_t)BTOT*CINV*HWV + b*PLV + t] = att;
}

// ---------------- fc B pre-scale + split: fw[n][k]*att[b][k] ----------------
__global__ void fcb_kernel(const float* __restrict__ fw)
{
    const int idx = blockIdx.x * 256 + threadIdx.x;   // grid 128 -> 32768 over [128][256]
    const int n = idx >> 8, k = idx & 255;
    const float w = fw[n*PLV + k];
#pragma unroll
    for (int b = 0; b < BTOT; b++) {
        const float v = w * g_att[b*PLV + k];
        const __nv_bfloat16 hi = __float2bfloat16(v);
        const size_t o = (size_t)(b*CINV + n)*PLV + k;
        g_fwbh[o] = hi;
        g_fwbl[o] = __float2bfloat16(v - __bfloat162float(hi));
    }
}

// ---------------- launch ----------------
extern "C" void kernel_launch(void* const* d_in, const int* in_sizes, int n_in,
                              void* d_out, int out_size)
{
    const float* x       = (const float*)d_in[0];
    const float* conv1_w = (const float*)d_in[1];
    const float* conv3_w = (const float*)d_in[2];
    const float* conv3_b = (const float*)d_in[3];
    const float* lower_w = (const float*)d_in[4];
    const float* lower_b = (const float*)d_in[5];
    const float* ca1_w   = (const float*)d_in[6];
    const float* ca2_w   = (const float*)d_in[7];
    const float* fc_w    = (const float*)d_in[8];
    const float* fc_b    = (const float*)d_in[9];
    const float* bases   = (const float*)d_in[10];
    float* out = (float*)d_out;

    static int smem_set = 0;
    if (!smem_set) {
        cudaFuncSetAttribute(conv1_mma_kernel,
                             cudaFuncAttributeMaxDynamicSharedMemorySize, LM_SMEM);
        cudaFuncSetAttribute(mma_pipe_kernel<1>,
                             cudaFuncAttributeMaxDynamicSharedMemorySize, PIPE_SMEM);
        cudaFuncSetAttribute(mma_pipe_kernel<2>,
                             cudaFuncAttributeMaxDynamicSharedMemorySize, PIPE_SMEM);
        smem_set = 1;
    }

    // device-global pointers usable from host via symbols not needed: pass via kernel args
    __nv_bfloat16 *xmh, *xml, *lwh, *lwl, *fth, *ftl, *fwh, *fwl;
    cudaGetSymbolAddress((void**)&xmh, g_xmh);
    cudaGetSymbolAddress((void**)&xml, g_xml);
    cudaGetSymbolAddress((void**)&lwh, g_lwh);
    cudaGetSymbolAddress((void**)&lwl, g_lwl);
    cudaGetSymbolAddress((void**)&fth, g_feath);
    cudaGetSymbolAddress((void**)&ftl, g_featl);
    cudaGetSymbolAddress((void**)&fwh, g_fwbh);
    cudaGetSymbolAddress((void**)&fwl, g_fwbl);

    init_kernel<<<256, 256>>>(lower_w);
    conv1_mma_kernel<<<dim3(MTOT/128, PLV/128), 256, LM_SMEM>>>(x, conv1_w);
    dw_kernel<<<MTOT/16, 256>>>(conv3_w, conv3_b);
    mma_pipe_kernel<1><<<dim3(MTOT/128, PLV/128), 256, PIPE_SMEM>>>(
        xmh, xml, lwh, lwl, lower_b, nullptr);
    em_fast<<<MTOT/16, 512>>>(bases);
    em_general<<<MTOT/8, 256>>>(bases);
    ca_kernel<<<BTOT, 256>>>(ca1_w, ca2_w, out);
    fcb_kernel<<<128, 256>>>(fc_w);
    mma_pipe_kernel<2><<<dim3(MTOT/128, 1), 256, PIPE_SMEM>>>(
        fth, ftl, fwh, fwl, fc_b, out);
}